// round 11
// baseline (speedup 1.0000x reference)
#include <cuda_runtime.h>
#include <cstdint>
#include <math.h>

#define T_    4096
#define H_    2048
#define I_    1408
#define E_    8
#define TWOI  2816

// ---------------- scratch ----------------
__device__ int8_t g_qin[(size_t)T_ * H_];
__device__ float  g_sin[T_];
__device__ int    g_cnt[E_];
__device__ int    g_tok[E_][T_];
__device__ float  g_gate_arr[E_][T_];
__device__ int8_t g_w13[(size_t)E_ * TWOI * H_];
__device__ int8_t g_w2[(size_t)E_ * H_ * I_];
__device__ float  g_act[(size_t)T_ * 2 * I_];
__device__ int8_t g_qact[(size_t)T_ * 2 * I_];
__device__ float  g_sa[T_ * 2];

// ---------------- helpers ----------------
__device__ __forceinline__ uint32_t smem_u32(const void* p) {
    uint32_t a;
    asm("{ .reg .u64 t; cvta.to.shared.u64 t, %1; cvt.u32.u64 %0, t; }" : "=r"(a) : "l"(p));
    return a;
}
#define CP16(dst, src) asm volatile("cp.async.cg.shared.global [%0], [%1], 16;" :: "r"(dst), "l"(src))
#define CP_COMMIT()    asm volatile("cp.async.commit_group;" ::: "memory")
#define CP_WAIT1()     asm volatile("cp.async.wait_group 1;" ::: "memory")

__device__ __forceinline__ void mma_s8(int* d, uint32_t a0, uint32_t a1, uint32_t a2, uint32_t a3,
                                       uint32_t b0, uint32_t b1) {
    asm volatile("mma.sync.aligned.m16n8k32.row.col.s32.s8.s8.s32 "
                 "{%0,%1,%2,%3}, {%4,%5,%6,%7}, {%8,%9}, {%0,%1,%2,%3};"
                 : "+r"(d[0]), "+r"(d[1]), "+r"(d[2]), "+r"(d[3])
                 : "r"(a0), "r"(a1), "r"(a2), "r"(a3), "r"(b0), "r"(b1));
}

// ---------------- weight conversion ----------------
__device__ __forceinline__ char4 conv_elem(const void* __restrict__ src, int idx, int mode) {
    if (mode == 1) {
        int4 v = ((const int4*)src)[idx];
        return make_char4((signed char)v.x, (signed char)v.y, (signed char)v.z, (signed char)v.w);
    } else if (mode == 2) {
        float4 v = ((const float4*)src)[idx];
        return make_char4((signed char)(int)v.x, (signed char)(int)v.y,
                          (signed char)(int)v.z, (signed char)(int)v.w);
    }
    return ((const char4*)src)[idx];
}
__device__ __forceinline__ int block_detect_mode(const void* src) {
    int tid = threadIdx.x;
    int v = ((const int*)src)[tid];
    float f = ((const float*)src)[tid];
    int n32 = __syncthreads_count(v >= -127 && v <= 127);
    int nf = __syncthreads_count(fabsf(f) <= 127.f && rintf(f) == f);
    return (n32 >= 250) ? 1 : ((nf >= 250) ? 2 : 0);
}
#define N4_W13 ((E_ * TWOI * H_) / 4)
#define N4_W2  ((E_ * H_ * I_) / 4)

__global__ __launch_bounds__(256) void convert_w13_kernel(const void* __restrict__ src) {
    int mode = block_detect_mode(src);
    for (int idx = blockIdx.x * 256 + threadIdx.x; idx < N4_W13; idx += gridDim.x * 256)
        ((char4*)g_w13)[idx] = conv_elem(src, idx, mode);
    if (blockIdx.x == 0 && threadIdx.x < E_) g_cnt[threadIdx.x] = 0;
}
__global__ __launch_bounds__(256) void convert_w2_kernel(const void* __restrict__ src) {
    int mode = block_detect_mode(src);
    for (int idx = blockIdx.x * 256 + threadIdx.x; idx < N4_W2; idx += gridDim.x * 256)
        ((char4*)g_w2)[idx] = conv_elem(src, idx, mode);
}

// ---------------- gate + quantize ----------------
__global__ __launch_bounds__(256) void gatequant_kernel(const float* __restrict__ hid,
                                                        const float* __restrict__ gw) {
    int t = blockIdx.x;
    const float* x = hid + (size_t)t * H_;
    float part[E_];
#pragma unroll
    for (int e = 0; e < E_; ++e) part[e] = 0.f;
    float amax = 0.f;
    for (int j = threadIdx.x; j < H_; j += 256) {
        float v = x[j];
        amax = fmaxf(amax, fabsf(v));
#pragma unroll
        for (int e = 0; e < E_; ++e) part[e] = fmaf(v, gw[e * H_ + j], part[e]);
    }
#pragma unroll
    for (int off = 16; off; off >>= 1) {
        amax = fmaxf(amax, __shfl_down_sync(0xffffffffu, amax, off));
#pragma unroll
        for (int e = 0; e < E_; ++e) part[e] += __shfl_down_sync(0xffffffffu, part[e], off);
    }
    __shared__ float red[8][E_ + 1];
    __shared__ float s_sh;
    int warp = threadIdx.x >> 5, lane = threadIdx.x & 31;
    if (lane == 0) {
#pragma unroll
        for (int e = 0; e < E_; ++e) red[warp][e] = part[e];
        red[warp][E_] = amax;
    }
    __syncthreads();
    if (threadIdx.x == 0) {
        float l[E_]; float am = 0.f;
#pragma unroll
        for (int e = 0; e < E_; ++e) l[e] = 0.f;
        for (int w = 0; w < 8; ++w) {
#pragma unroll
            for (int e = 0; e < E_; ++e) l[e] += red[w][e];
            am = fmaxf(am, red[w][E_]);
        }
        float b1 = -1e30f, b2 = -1e30f; int i1 = 0, i2 = 0;
#pragma unroll
        for (int e = 0; e < E_; ++e) {
            float v = l[e];
            if (v > b1) { b2 = b1; i2 = i1; b1 = v; i1 = e; }
            else if (v > b2) { b2 = v; i2 = e; }
        }
        float e2v = expf(b2 - b1);
        float inv = __fdiv_rn(1.f, 1.f + e2v);
        float s = fmaxf(__fdiv_rn(am, 127.f), 1e-8f);
        g_sin[t] = s; s_sh = s;
        int p0 = atomicAdd(&g_cnt[i1], 1);
        g_tok[i1][p0] = t * 2 + 0; g_gate_arr[i1][p0] = inv;
        int p1 = atomicAdd(&g_cnt[i2], 1);
        g_tok[i2][p1] = t * 2 + 1; g_gate_arr[i2][p1] = e2v * inv;
    }
    __syncthreads();
    float s = s_sh;
    const float4* xv = (const float4*)x;
    char4* q = (char4*)(g_qin + (size_t)t * H_);
    for (int j = threadIdx.x; j < H_ / 4; j += 256) {
        float4 v = xv[j];
        float a = fminf(fmaxf(rintf(__fdiv_rn(v.x, s)), -127.f), 127.f);
        float b = fminf(fmaxf(rintf(__fdiv_rn(v.y, s)), -127.f), 127.f);
        float c = fminf(fmaxf(rintf(__fdiv_rn(v.z, s)), -127.f), 127.f);
        float d = fminf(fmaxf(rintf(__fdiv_rn(v.w, s)), -127.f), 127.f);
        q[j] = make_char4((signed char)a, (signed char)b, (signed char)c, (signed char)d);
    }
}

// ===========================================================================
// GEMM1 fused-role: every warp does mma (i-cols 0-31 slice) AND dp4a
// (i-cols 32-63 slice). M=64. 3-stage cp.async. grid (64, E, 22).
// ===========================================================================
#define PAD    80
#define ST1    15360
#define G1_META (3 * ST1)
#define G1_SMEM (G1_META + 768)
#define NS1    32

__global__ __launch_bounds__(256, 2) void gemm1_mma(const float* __restrict__ s13_all) {
    int e = blockIdx.y;
    int cnt = g_cnt[e];
    int m0 = blockIdx.x * 64;
    if (m0 >= cnt) return;
    int nt = min(64, cnt - m0);
    int z = blockIdx.z;

    extern __shared__ char smem[];
    uint32_t sb = smem_u32(smem);
    int* dst_s = (int*)(smem + G1_META);
    float* sin_s = (float*)(smem + G1_META + 256);
    int tid = threadIdx.x;

    if (tid < 64) {
        int packed = (tid < nt) ? g_tok[e][m0 + tid] : g_tok[e][m0];
        dst_s[tid] = packed;
        sin_s[tid] = g_sin[packed >> 1];
    }
    __syncthreads();

    const int8_t* w13 = g_w13 + (size_t)e * TWOI * H_;
    int rA = tid >> 2, cA = (tid & 3) * 16;
    const int8_t* srcA = g_qin + (size_t)(dst_s[rA] >> 1) * H_ + cA;
    int rB = tid >> 1, cB = (tid & 1) * 32;
    const int8_t* srcB = (rB < 64)
        ? w13 + (size_t)(z * 64 + rB) * H_ + cB
        : w13 + (size_t)(I_ + z * 64 + (rB - 64)) * H_ + cB;
    uint32_t dA = sb + rA * PAD + cA;
    uint32_t dB = sb + 5120 + rB * PAD + cB;

#pragma unroll
    for (int s = 0; s < 2; ++s) {
        CP16(dA + s * ST1, srcA + s * 64);
        CP16(dB + s * ST1, srcB + s * 64);
        CP16(dB + s * ST1 + 16, srcB + s * 64 + 16);
        CP_COMMIT();
    }

    int warp = tid >> 5, lane = tid & 31;
    int wm = warp & 1, wv = warp >> 1;            // mma: 2m x 4n(8-col tiles)
    int sub = lane >> 2, q4 = (lane & 3) * 4;
    int dcol = 32 + warp * 4 + (lane & 3);        // dp4a: 4 cols/warp
    int rg = lane >> 2;                           // 8 row-groups x 8 rows

    int mg[2][4], mu[2][4];                       // mma acc (mt x 4)
    int dg[8], du[8];                             // dp4a acc (8 rows)
#pragma unroll
    for (int mt = 0; mt < 2; ++mt)
#pragma unroll
        for (int r = 0; r < 4; ++r) { mg[mt][r] = 0; mu[mt][r] = 0; }
#pragma unroll
    for (int r = 0; r < 8; ++r) { dg[r] = 0; du[r] = 0; }

    for (int ks = 0; ks < NS1; ++ks) {
        CP_WAIT1();
        __syncthreads();
        const char* As = smem + (ks % 3) * ST1;
        const char* Bs = As + 5120;
#pragma unroll
        for (int kk = 0; kk < 64; kk += 32) {
            // --- mma slice: tile wv (cols wv*8..+8), both g and u ---
            uint32_t a[2][4];
#pragma unroll
            for (int mt = 0; mt < 2; ++mt) {
                const char* ar = As + (wm * 32 + mt * 16 + sub) * PAD + kk + q4;
                a[mt][0] = *(const uint32_t*)(ar);
                a[mt][1] = *(const uint32_t*)(ar + 8 * PAD);
                a[mt][2] = *(const uint32_t*)(ar + 16);
                a[mt][3] = *(const uint32_t*)(ar + 8 * PAD + 16);
            }
            {
                const char* bg = Bs + (wv * 8 + sub) * PAD + kk + q4;
                uint32_t g0 = *(const uint32_t*)(bg);
                uint32_t g1 = *(const uint32_t*)(bg + 16);
                uint32_t u0 = *(const uint32_t*)(bg + 64 * PAD);
                uint32_t u1 = *(const uint32_t*)(bg + 64 * PAD + 16);
#pragma unroll
                for (int mt = 0; mt < 2; ++mt) {
                    mma_s8(mg[mt], a[mt][0], a[mt][1], a[mt][2], a[mt][3], g0, g1);
                    mma_s8(mu[mt], a[mt][0], a[mt][1], a[mt][2], a[mt][3], u0, u1);
                }
            }
            // --- dp4a slice: 2 j-blocks per kk ---
#pragma unroll
            for (int jj = 0; jj < 2; ++jj) {
                int j = (kk >> 5) * 2 + jj;
                int kk4 = ((rg + j) & 3) * 16;
                int4 bgv = *(const int4*)(Bs + dcol * PAD + kk4);
                int4 buv = *(const int4*)(Bs + (64 + dcol) * PAD + kk4);
#pragma unroll
                for (int r = 0; r < 8; ++r) {
                    int4 av = *(const int4*)(As + (rg * 8 + r) * PAD + kk4);
                    dg[r] = __dp4a(av.x, bgv.x, dg[r]);
                    dg[r] = __dp4a(av.y, bgv.y, dg[r]);
                    dg[r] = __dp4a(av.z, bgv.z, dg[r]);
                    dg[r] = __dp4a(av.w, bgv.w, dg[r]);
                    du[r] = __dp4a(av.x, buv.x, du[r]);
                    du[r] = __dp4a(av.y, buv.y, du[r]);
                    du[r] = __dp4a(av.z, buv.z, du[r]);
                    du[r] = __dp4a(av.w, buv.w, du[r]);
                }
            }
        }
        if (ks + 2 < NS1) {
            int s = (ks + 2) % 3;
            int kb = (ks + 2) * 64;
            CP16(dA + s * ST1, srcA + kb);
            CP16(dB + s * ST1, srcB + kb);
            CP16(dB + s * ST1 + 16, srcB + kb + 16);
        }
        CP_COMMIT();
    }

    const float* s13 = s13_all + (size_t)e * TWOI + z * 64;
    // --- mma epilogue (cols 0-31) ---
    {
        int col = wv * 8 + (lane & 3) * 2;
        float sg0 = s13[col], sg1 = s13[col + 1];
        float su0 = s13[col + I_], su1 = s13[col + I_ + 1];
#pragma unroll
        for (int mt = 0; mt < 2; ++mt) {
#pragma unroll
            for (int h2 = 0; h2 < 2; ++h2) {
                int row = wm * 32 + mt * 16 + sub + h2 * 8;
                if (row < nt) {
                    float si = sin_s[row];
                    float g0 = (float)mg[mt][h2 * 2 + 0] * si * sg0;
                    float g1 = (float)mg[mt][h2 * 2 + 1] * si * sg1;
                    float u0 = (float)mu[mt][h2 * 2 + 0] * si * su0;
                    float u1 = (float)mu[mt][h2 * 2 + 1] * si * su1;
                    float a0 = g0 * __fdiv_rn(1.f, 1.f + expf(-g0)) * u0;
                    float a1 = g1 * __fdiv_rn(1.f, 1.f + expf(-g1)) * u1;
                    *(float2*)(g_act + (size_t)dst_s[row] * I_ + z * 64 + col) =
                        make_float2(a0, a1);
                }
            }
        }
    }
    // --- dp4a epilogue (cols 32-63) ---
    {
        float sg = s13[dcol], su = s13[dcol + I_];
#pragma unroll
        for (int r = 0; r < 8; ++r) {
            int row = rg * 8 + r;
            if (row < nt) {
                float si = sin_s[row];
                float g = (float)dg[r] * si * sg;
                float u = (float)du[r] * si * su;
                g_act[(size_t)dst_s[row] * I_ + z * 64 + dcol] =
                    g * __fdiv_rn(1.f, 1.f + expf(-g)) * u;
            }
        }
    }
}

// ---------------- requant ----------------
__global__ __launch_bounds__(128) void requant_kernel() {
    int dst = blockIdx.x;
    const float* a = g_act + (size_t)dst * I_;
    int tid = threadIdx.x;
    float m = 0.f;
    for (int i = tid; i < I_; i += 128) m = fmaxf(m, fabsf(a[i]));
    __shared__ float red[4];
#pragma unroll
    for (int off = 16; off; off >>= 1) m = fmaxf(m, __shfl_down_sync(0xffffffffu, m, off));
    if ((tid & 31) == 0) red[tid >> 5] = m;
    __syncthreads();
    float mm = fmaxf(fmaxf(red[0], red[1]), fmaxf(red[2], red[3]));
    float sa = fmaxf(__fdiv_rn(mm, 127.f), 1e-8f);
    if (tid == 0) g_sa[dst] = sa;
    int8_t* q = g_qact + (size_t)dst * I_;
    for (int i = tid; i < I_; i += 128) {
        float v = fminf(fmaxf(rintf(__fdiv_rn(a[i], sa)), -127.f), 127.f);
        q[i] = (int8_t)v;
    }
}

// ---------------- zero output ----------------
__global__ __launch_bounds__(256) void zero_out_kernel(float* __restrict__ out) {
    size_t idx = (size_t)blockIdx.x * 256 + threadIdx.x;
    ((float4*)out)[idx] = make_float4(0.f, 0.f, 0.f, 0.f);
}

// ===========================================================================
// GEMM2 fused-role: every warp does mma (h-cols 0-63 slice) AND dp4a
// (h-cols 64-127 slice). grid (64, E, 16). atomicAdd into out.
// ===========================================================================
#define ST2    15360
#define G2_META (3 * ST2)
#define G2_SMEM (G2_META + 1024)
#define NS2    22

__global__ __launch_bounds__(256, 2) void gemm2_mma(const float* __restrict__ s2_all,
                                                    float* __restrict__ out) {
    int e = blockIdx.y;
    int cnt = g_cnt[e];
    int m0 = blockIdx.x * 64;
    if (m0 >= cnt) return;
    int nt = min(64, cnt - m0);
    int z = blockIdx.z;

    extern __shared__ char smem[];
    uint32_t sb = smem_u32(smem);
    int* dst_s = (int*)(smem + G2_META);
    float* sc_s = (float*)(smem + G2_META + 256);
    int tid = threadIdx.x;

    if (tid < 64) {
        int packed; float gv;
        if (tid < nt) { packed = g_tok[e][m0 + tid]; gv = g_gate_arr[e][m0 + tid]; }
        else          { packed = g_tok[e][m0];       gv = 0.f; }
        dst_s[tid] = packed;
        sc_s[tid] = gv * g_sa[packed];
    }
    __syncthreads();

    const int8_t* w2 = g_w2 + (size_t)e * H_ * I_;
    int rA = tid >> 2, cA = (tid & 3) * 16;
    const int8_t* srcA = g_qact + (size_t)dst_s[rA] * I_ + cA;
    int rB = tid >> 1, cB = (tid & 1) * 32;
    const int8_t* srcB = w2 + (size_t)(z * 128 + rB) * I_ + cB;
    uint32_t dA = sb + rA * PAD + cA;
    uint32_t dB = sb + 5120 + rB * PAD + cB;

#pragma unroll
    for (int s = 0; s < 2; ++s) {
        CP16(dA + s * ST2, srcA + s * 64);
        CP16(dB + s * ST2, srcB + s * 64);
        CP16(dB + s * ST2 + 16, srcB + s * 64 + 16);
        CP_COMMIT();
    }

    int warp = tid >> 5, lane = tid & 31;
    int wm = warp & 1, wv = warp >> 1;            // mma: 2m x 4n(16-col)
    int sub = lane >> 2, q4 = (lane & 3) * 4;
    int dcol = 64 + warp * 8 + (lane & 7);        // dp4a: 8 cols/warp
    int rg = lane >> 3;                           // 4 row-groups x 16 rows

    int ma[2][2][4];                              // mt x n8 x 4
    int da[16];
#pragma unroll
    for (int mt = 0; mt < 2; ++mt)
#pragma unroll
        for (int n8 = 0; n8 < 2; ++n8)
#pragma unroll
            for (int r = 0; r < 4; ++r) ma[mt][n8][r] = 0;
#pragma unroll
    for (int r = 0; r < 16; ++r) da[r] = 0;

    for (int ks = 0; ks < NS2; ++ks) {
        CP_WAIT1();
        __syncthreads();
        const char* As = smem + (ks % 3) * ST2;
        const char* Bs = As + 5120;
#pragma unroll
        for (int kk = 0; kk < 64; kk += 32) {
            uint32_t a[2][4];
#pragma unroll
            for (int mt = 0; mt < 2; ++mt) {
                const char* ar = As + (wm * 32 + mt * 16 + sub) * PAD + kk + q4;
                a[mt][0] = *(const uint32_t*)(ar);
                a[mt][1] = *(const uint32_t*)(ar + 8 * PAD);
                a[mt][2] = *(const uint32_t*)(ar + 16);
                a[mt][3] = *(const uint32_t*)(ar + 8 * PAD + 16);
            }
#pragma unroll
            for (int n8 = 0; n8 < 2; ++n8) {
                const char* br = Bs + (wv * 16 + n8 * 8 + sub) * PAD + kk + q4;
                uint32_t b0 = *(const uint32_t*)(br);
                uint32_t b1 = *(const uint32_t*)(br + 16);
#pragma unroll
                for (int mt = 0; mt < 2; ++mt)
                    mma_s8(ma[mt][n8], a[mt][0], a[mt][1], a[mt][2], a[mt][3], b0, b1);
            }
            // dp4a slice: 2 j-blocks per kk
#pragma unroll
            for (int jj = 0; jj < 2; ++jj) {
                int j = (kk >> 5) * 2 + jj;
                int kk4 = ((rg + j) & 3) * 16;
                int4 bv = *(const int4*)(Bs + dcol * PAD + kk4);
#pragma unroll
                for (int r = 0; r < 16; ++r) {
                    int4 av = *(const int4*)(As + (rg * 16 + r) * PAD + kk4);
                    da[r] = __dp4a(av.x, bv.x, da[r]);
                    da[r] = __dp4a(av.y, bv.y, da[r]);
                    da[r] = __dp4a(av.z, bv.z, da[r]);
                    da[r] = __dp4a(av.w, bv.w, da[r]);
                }
            }
        }
        if (ks + 2 < NS2) {
            int s = (ks + 2) % 3;
            int kb = (ks + 2) * 64;
            CP16(dA + s * ST2, srcA + kb);
            CP16(dB + s * ST2, srcB + kb);
            CP16(dB + s * ST2 + 16, srcB + kb + 16);
        }
        CP_COMMIT();
    }

    const float* s2w = s2_all + (size_t)e * H_ + z * 128;
    // --- mma epilogue (cols 0-63) ---
#pragma unroll
    for (int mt = 0; mt < 2; ++mt) {
#pragma unroll
        for (int n8 = 0; n8 < 2; ++n8) {
            int col = wv * 16 + n8 * 8 + (lane & 3) * 2;
            float w0 = s2w[col], w1 = s2w[col + 1];
#pragma unroll
            for (int h2 = 0; h2 < 2; ++h2) {
                int row = wm * 32 + mt * 16 + sub + h2 * 8;
                if (row < nt) {
                    float sc = sc_s[row];
                    int t = dst_s[row] >> 1;
                    float* orow = out + (size_t)t * H_ + z * 128 + col;
                    atomicAdd(orow, (float)ma[mt][n8][h2 * 2 + 0] * sc * w0);
                    atomicAdd(orow + 1, (float)ma[mt][n8][h2 * 2 + 1] * sc * w1);
                }
            }
        }
    }
    // --- dp4a epilogue (cols 64-127) ---
    {
        float w0 = s2w[dcol];
#pragma unroll
        for (int r = 0; r < 16; ++r) {
            int row = rg * 16 + r;
            if (row < nt) {
                float sc = sc_s[row];
                int t = dst_s[row] >> 1;
                atomicAdd(out + (size_t)t * H_ + z * 128 + dcol,
                          (float)da[r] * sc * w0);
            }
        }
    }
}

// ---------------------------------------------------------------------------
extern "C" void kernel_launch(void* const* d_in, const int* in_sizes, int n_in,
                              void* d_out, int out_size) {
    const float* hid = nullptr;
    const float* gw = nullptr;
    const void* w13raw = nullptr;
    const float* s13 = nullptr;
    const void* w2raw = nullptr;
    const float* s2 = nullptr;
    for (int i = 0; i < n_in; ++i) {
        long long s = in_sizes[i];
        if (s == 8388608LL || s == 33554432LL) hid = (const float*)d_in[i];
        else if (s == 46137344LL || s == 184549376LL) w13raw = d_in[i];
        else if (s == 22528LL || s == 90112LL) s13 = (const float*)d_in[i];
        else if (s == 23068672LL || s == 92274688LL) w2raw = d_in[i];
        else if (s == 16384LL || s == 65536LL) {
            if (!gw) gw = (const float*)d_in[i];
            else s2 = (const float*)d_in[i];
        }
    }
    if (n_in >= 6) {
        if (!hid)    hid = (const float*)d_in[0];
        if (!gw)     gw = (const float*)d_in[1];
        if (!w13raw) w13raw = d_in[2];
        if (!s13)    s13 = (const float*)d_in[3];
        if (!w2raw)  w2raw = d_in[4];
        if (!s2)     s2 = (const float*)d_in[5];
    }
    float* out = (float*)d_out;

    cudaFuncSetAttribute(gemm1_mma, cudaFuncAttributeMaxDynamicSharedMemorySize, G1_SMEM);
    cudaFuncSetAttribute(gemm2_mma, cudaFuncAttributeMaxDynamicSharedMemorySize, G2_SMEM);

    convert_w13_kernel<<<8192, 256>>>(w13raw);            // 1
    convert_w2_kernel<<<8192, 256>>>(w2raw);              // 2
    gatequant_kernel<<<T_, 256>>>(hid, gw);               // 3
    dim3 g1(64, E_, 22);
    gemm1_mma<<<g1, 256, G1_SMEM>>>(s13);                 // 4 (profiled slot)
    requant_kernel<<<T_ * 2, 128>>>();                    // 5
    zero_out_kernel<<<(T_ * H_) / 1024, 256>>>(out);      // 6
    dim3 g2(64, E_, 16);
    gemm2_mma<<<g2, 256, G2_SMEM>>>(s2, out);             // 7
}

// round 13
// speedup vs baseline: 1.0091x; 1.0091x over previous
#include <cuda_runtime.h>
#include <cstdint>
#include <math.h>

#define T_    4096
#define H_    2048
#define I_    1408
#define E_    8
#define TWOI  2816

// ---------------- scratch ----------------
__device__ int8_t g_qin[(size_t)T_ * H_];
__device__ float  g_sin[T_];
__device__ int    g_cnt[E_];
__device__ int    g_tok[E_][T_];
__device__ float  g_gate_arr[E_][T_];
__device__ int8_t g_w13[(size_t)E_ * TWOI * H_];
__device__ int8_t g_w2[(size_t)E_ * H_ * I_];
__device__ float  g_act[(size_t)T_ * 2 * I_];
__device__ int8_t g_qact[(size_t)T_ * 2 * I_];
__device__ float  g_sa[T_ * 2];

// ---------------- helpers ----------------
__device__ __forceinline__ uint32_t smem_u32(const void* p) {
    uint32_t a;
    asm("{ .reg .u64 t; cvta.to.shared.u64 t, %1; cvt.u32.u64 %0, t; }" : "=r"(a) : "l"(p));
    return a;
}
#define CP16(dst, src) asm volatile("cp.async.cg.shared.global [%0], [%1], 16;" :: "r"(dst), "l"(src))
#define CP_COMMIT()    asm volatile("cp.async.commit_group;" ::: "memory")
#define CP_WAIT1()     asm volatile("cp.async.wait_group 1;" ::: "memory")

__device__ __forceinline__ void mma_s8(int* d, uint32_t a0, uint32_t a1, uint32_t a2, uint32_t a3,
                                       uint32_t b0, uint32_t b1) {
    asm volatile("mma.sync.aligned.m16n8k32.row.col.s32.s8.s8.s32 "
                 "{%0,%1,%2,%3}, {%4,%5,%6,%7}, {%8,%9}, {%0,%1,%2,%3};"
                 : "+r"(d[0]), "+r"(d[1]), "+r"(d[2]), "+r"(d[3])
                 : "r"(a0), "r"(a1), "r"(a2), "r"(a3), "r"(b0), "r"(b1));
}

// ---------------- weight conversion ----------------
__device__ __forceinline__ char4 conv_elem(const void* __restrict__ src, int idx, int mode) {
    if (mode == 1) {
        int4 v = ((const int4*)src)[idx];
        return make_char4((signed char)v.x, (signed char)v.y, (signed char)v.z, (signed char)v.w);
    } else if (mode == 2) {
        float4 v = ((const float4*)src)[idx];
        return make_char4((signed char)(int)v.x, (signed char)(int)v.y,
                          (signed char)(int)v.z, (signed char)(int)v.w);
    }
    return ((const char4*)src)[idx];
}
__device__ __forceinline__ int block_detect_mode(const void* src) {
    int tid = threadIdx.x;
    int v = ((const int*)src)[tid];
    float f = ((const float*)src)[tid];
    int n32 = __syncthreads_count(v >= -127 && v <= 127);
    int nf = __syncthreads_count(fabsf(f) <= 127.f && rintf(f) == f);
    return (n32 >= 250) ? 1 : ((nf >= 250) ? 2 : 0);
}
#define N4_W13 ((E_ * TWOI * H_) / 4)
#define N4_W2  ((E_ * H_ * I_) / 4)

__global__ __launch_bounds__(256) void convert_w13_kernel(const void* __restrict__ src) {
    int mode = block_detect_mode(src);
    for (int idx = blockIdx.x * 256 + threadIdx.x; idx < N4_W13; idx += gridDim.x * 256)
        ((char4*)g_w13)[idx] = conv_elem(src, idx, mode);
    if (blockIdx.x == 0 && threadIdx.x < E_) g_cnt[threadIdx.x] = 0;
}
__global__ __launch_bounds__(256) void convert_w2_kernel(const void* __restrict__ src) {
    int mode = block_detect_mode(src);
    for (int idx = blockIdx.x * 256 + threadIdx.x; idx < N4_W2; idx += gridDim.x * 256)
        ((char4*)g_w2)[idx] = conv_elem(src, idx, mode);
}

// ---------------- gate + quantize ----------------
__global__ __launch_bounds__(256) void gatequant_kernel(const float* __restrict__ hid,
                                                        const float* __restrict__ gw) {
    int t = blockIdx.x;
    const float* x = hid + (size_t)t * H_;
    float part[E_];
#pragma unroll
    for (int e = 0; e < E_; ++e) part[e] = 0.f;
    float amax = 0.f;
    for (int j = threadIdx.x; j < H_; j += 256) {
        float v = x[j];
        amax = fmaxf(amax, fabsf(v));
#pragma unroll
        for (int e = 0; e < E_; ++e) part[e] = fmaf(v, gw[e * H_ + j], part[e]);
    }
#pragma unroll
    for (int off = 16; off; off >>= 1) {
        amax = fmaxf(amax, __shfl_down_sync(0xffffffffu, amax, off));
#pragma unroll
        for (int e = 0; e < E_; ++e) part[e] += __shfl_down_sync(0xffffffffu, part[e], off);
    }
    __shared__ float red[8][E_ + 1];
    __shared__ float s_sh;
    int warp = threadIdx.x >> 5, lane = threadIdx.x & 31;
    if (lane == 0) {
#pragma unroll
        for (int e = 0; e < E_; ++e) red[warp][e] = part[e];
        red[warp][E_] = amax;
    }
    __syncthreads();
    if (threadIdx.x == 0) {
        float l[E_]; float am = 0.f;
#pragma unroll
        for (int e = 0; e < E_; ++e) l[e] = 0.f;
        for (int w = 0; w < 8; ++w) {
#pragma unroll
            for (int e = 0; e < E_; ++e) l[e] += red[w][e];
            am = fmaxf(am, red[w][E_]);
        }
        float b1 = -1e30f, b2 = -1e30f; int i1 = 0, i2 = 0;
#pragma unroll
        for (int e = 0; e < E_; ++e) {
            float v = l[e];
            if (v > b1) { b2 = b1; i2 = i1; b1 = v; i1 = e; }
            else if (v > b2) { b2 = v; i2 = e; }
        }
        float e2v = expf(b2 - b1);
        float inv = __fdiv_rn(1.f, 1.f + e2v);
        float s = fmaxf(__fdiv_rn(am, 127.f), 1e-8f);
        g_sin[t] = s; s_sh = s;
        int p0 = atomicAdd(&g_cnt[i1], 1);
        g_tok[i1][p0] = t * 2 + 0; g_gate_arr[i1][p0] = inv;
        int p1 = atomicAdd(&g_cnt[i2], 1);
        g_tok[i2][p1] = t * 2 + 1; g_gate_arr[i2][p1] = e2v * inv;
    }
    __syncthreads();
    float s = s_sh;
    const float4* xv = (const float4*)x;
    char4* q = (char4*)(g_qin + (size_t)t * H_);
    for (int j = threadIdx.x; j < H_ / 4; j += 256) {
        float4 v = xv[j];
        float a = fminf(fmaxf(rintf(__fdiv_rn(v.x, s)), -127.f), 127.f);
        float b = fminf(fmaxf(rintf(__fdiv_rn(v.y, s)), -127.f), 127.f);
        float c = fminf(fmaxf(rintf(__fdiv_rn(v.z, s)), -127.f), 127.f);
        float d = fminf(fmaxf(rintf(__fdiv_rn(v.w, s)), -127.f), 127.f);
        q[j] = make_char4((signed char)a, (signed char)b, (signed char)c, (signed char)d);
    }
}

// ===========================================================================
// GEMM1: M=64 x N=88 (mma: 56 cols via 4 warps each 16-row band x 7 tiles;
// dp4a: 32 cols via 4 warps x 8 cols). 3-stage cp.async. grid (64, E, 16).
// ===========================================================================
#define PAD    80
#define NB1    88
#define ST1    (64 * PAD + 2 * NB1 * PAD)     // 5120 + 14080 = 19200
#define G1_META (3 * ST1)
#define G1_SMEM (G1_META + 768)
#define NS1    32
#define NCH1   ((64 + 2 * NB1) * 4)           // 960 16B chunks per stage

__global__ __launch_bounds__(256, 2) void gemm1_mma(const float* __restrict__ s13_all) {
    int e = blockIdx.y;
    int cnt = g_cnt[e];
    int m0 = blockIdx.x * 64;
    if (m0 >= cnt) return;
    int nt = min(64, cnt - m0);
    int z = blockIdx.z;           // 88-col band

    extern __shared__ char smem[];
    uint32_t sb = smem_u32(smem);
    int* dst_s = (int*)(smem + G1_META);
    float* sin_s = (float*)(smem + G1_META + 256);
    int tid = threadIdx.x;

    if (tid < 64) {
        int packed = (tid < nt) ? g_tok[e][m0 + tid] : g_tok[e][m0];
        dst_s[tid] = packed;
        sin_s[tid] = g_sin[packed >> 1];
    }
    __syncthreads();

    const int8_t* w13 = g_w13 + (size_t)e * TWOI * H_;
    // per-thread staging assignment: up to 4 chunks (padded w/ duplicates)
    const int8_t* csrc[4]; uint32_t cdoff[4];
    {
        int nch = 0;
        for (int i = tid; i < NCH1; i += 256) {
            if (i < 256) {
                int r = i >> 2, c = (i & 3) * 16;
                csrc[nch] = g_qin + (size_t)(dst_s[r] >> 1) * H_ + c;
                cdoff[nch] = r * PAD + c;
            } else {
                int j2 = i - 256;
                int rb = j2 >> 2, c = (j2 & 3) * 16;
                const int8_t* base = (rb < NB1)
                    ? w13 + (size_t)(z * NB1 + rb) * H_ + c
                    : w13 + (size_t)(I_ + z * NB1 + (rb - NB1)) * H_ + c;
                csrc[nch] = base;
                cdoff[nch] = 64 * PAD + rb * PAD + c;
            }
            nch++;
        }
        while (nch < 4) { csrc[nch] = csrc[0]; cdoff[nch] = cdoff[0]; nch++; }
    }

#pragma unroll
    for (int s = 0; s < 2; ++s) {
#pragma unroll
        for (int c = 0; c < 4; ++c) CP16(sb + s * ST1 + cdoff[c], csrc[c] + s * 64);
        CP_COMMIT();
    }

    int warp = tid >> 5, lane = tid & 31;

    if (warp < 4) {
        // ---- mma role: cols [0,56), rows [warp*16, warp*16+16) ----
        int sub = lane >> 2, q4 = (lane & 3) * 4;
        int accg[7][4], accu[7][4];
#pragma unroll
        for (int n8 = 0; n8 < 7; ++n8)
#pragma unroll
            for (int r = 0; r < 4; ++r) { accg[n8][r] = 0; accu[n8][r] = 0; }

        for (int ks = 0; ks < NS1; ++ks) {
            CP_WAIT1();
            __syncthreads();
            const char* As = smem + (ks % 3) * ST1;
            const char* Bs = As + 64 * PAD;
#pragma unroll
            for (int kk = 0; kk < 64; kk += 32) {
                const char* ar = As + (warp * 16 + sub) * PAD + kk + q4;
                uint32_t a0 = *(const uint32_t*)(ar);
                uint32_t a1 = *(const uint32_t*)(ar + 8 * PAD);
                uint32_t a2 = *(const uint32_t*)(ar + 16);
                uint32_t a3 = *(const uint32_t*)(ar + 8 * PAD + 16);
#pragma unroll
                for (int n8 = 0; n8 < 7; ++n8) {
                    const char* bg = Bs + (n8 * 8 + sub) * PAD + kk + q4;
                    uint32_t g0 = *(const uint32_t*)(bg);
                    uint32_t g1 = *(const uint32_t*)(bg + 16);
                    uint32_t u0 = *(const uint32_t*)(bg + NB1 * PAD);
                    uint32_t u1 = *(const uint32_t*)(bg + NB1 * PAD + 16);
                    mma_s8(accg[n8], a0, a1, a2, a3, g0, g1);
                    mma_s8(accu[n8], a0, a1, a2, a3, u0, u1);
                }
            }
            if (ks + 2 < NS1) {
                int s = (ks + 2) % 3;
                int kb = (ks + 2) * 64;
#pragma unroll
                for (int c = 0; c < 4; ++c) CP16(sb + s * ST1 + cdoff[c], csrc[c] + kb);
            }
            CP_COMMIT();
        }

        const float* s13 = s13_all + (size_t)e * TWOI + z * NB1;
#pragma unroll
        for (int n8 = 0; n8 < 7; ++n8) {
            int col = n8 * 8 + (lane & 3) * 2;
            float sg0 = s13[col], sg1 = s13[col + 1];
            float su0 = s13[col + I_], su1 = s13[col + I_ + 1];
#pragma unroll
            for (int h2 = 0; h2 < 2; ++h2) {
                int row = warp * 16 + sub + h2 * 8;
                if (row < nt) {
                    float si = sin_s[row];
                    float g0 = (float)accg[n8][h2 * 2 + 0] * si * sg0;
                    float g1 = (float)accg[n8][h2 * 2 + 1] * si * sg1;
                    float u0 = (float)accu[n8][h2 * 2 + 0] * si * su0;
                    float u1 = (float)accu[n8][h2 * 2 + 1] * si * su1;
                    float a0 = g0 * __fdiv_rn(1.f, 1.f + expf(-g0)) * u0;
                    float a1 = g1 * __fdiv_rn(1.f, 1.f + expf(-g1)) * u1;
                    *(float2*)(g_act + (size_t)dst_s[row] * I_ + z * NB1 + col) =
                        make_float2(a0, a1);
                }
            }
        }
    } else {
        // ---- dp4a role: cols [56,88) ----
        int dcol = 56 + (warp - 4) * 8 + (lane & 7);
        int rg = lane >> 3;                       // 4 groups x 16 rows
        int accg[16], accu[16];
#pragma unroll
        for (int r = 0; r < 16; ++r) { accg[r] = 0; accu[r] = 0; }

        for (int ks = 0; ks < NS1; ++ks) {
            CP_WAIT1();
            __syncthreads();
            const char* As = smem + (ks % 3) * ST1;
            const char* Bs = As + 64 * PAD;
#pragma unroll
            for (int j = 0; j < 4; ++j) {
                int kk4 = ((rg + j) & 3) * 16;
                int4 bg = *(const int4*)(Bs + dcol * PAD + kk4);
                int4 bu = *(const int4*)(Bs + (NB1 + dcol) * PAD + kk4);
#pragma unroll
                for (int r = 0; r < 16; ++r) {
                    int4 av = *(const int4*)(As + (rg * 16 + r) * PAD + kk4);
                    accg[r] = __dp4a(av.x, bg.x, accg[r]);
                    accg[r] = __dp4a(av.y, bg.y, accg[r]);
                    accg[r] = __dp4a(av.z, bg.z, accg[r]);
                    accg[r] = __dp4a(av.w, bg.w, accg[r]);
                    accu[r] = __dp4a(av.x, bu.x, accu[r]);
                    accu[r] = __dp4a(av.y, bu.y, accu[r]);
                    accu[r] = __dp4a(av.z, bu.z, accu[r]);
                    accu[r] = __dp4a(av.w, bu.w, accu[r]);
                }
            }
            if (ks + 2 < NS1) {
                int s = (ks + 2) % 3;
                int kb = (ks + 2) * 64;
#pragma unroll
                for (int c = 0; c < 4; ++c) CP16(sb + s * ST1 + cdoff[c], csrc[c] + kb);
            }
            CP_COMMIT();
        }

        const float* s13 = s13_all + (size_t)e * TWOI + z * NB1;
        float sg = s13[dcol], su = s13[dcol + I_];
#pragma unroll
        for (int r = 0; r < 16; ++r) {
            int row = rg * 16 + r;
            if (row < nt) {
                float si = sin_s[row];
                float g = (float)accg[r] * si * sg;
                float u = (float)accu[r] * si * su;
                g_act[(size_t)dst_s[row] * I_ + z * NB1 + dcol] =
                    g * __fdiv_rn(1.f, 1.f + expf(-g)) * u;
            }
        }
    }
}

// ---------------- requant ----------------
__global__ __launch_bounds__(128) void requant_kernel() {
    int dst = blockIdx.x;
    const float* a = g_act + (size_t)dst * I_;
    int tid = threadIdx.x;
    float m = 0.f;
    for (int i = tid; i < I_; i += 128) m = fmaxf(m, fabsf(a[i]));
    __shared__ float red[4];
#pragma unroll
    for (int off = 16; off; off >>= 1) m = fmaxf(m, __shfl_down_sync(0xffffffffu, m, off));
    if ((tid & 31) == 0) red[tid >> 5] = m;
    __syncthreads();
    float mm = fmaxf(fmaxf(red[0], red[1]), fmaxf(red[2], red[3]));
    float sa = fmaxf(__fdiv_rn(mm, 127.f), 1e-8f);
    if (tid == 0) g_sa[dst] = sa;
    int8_t* q = g_qact + (size_t)dst * I_;
    for (int i = tid; i < I_; i += 128) {
        float v = fminf(fmaxf(rintf(__fdiv_rn(a[i], sa)), -127.f), 127.f);
        q[i] = (int8_t)v;
    }
}

// ---------------- zero output ----------------
__global__ __launch_bounds__(256) void zero_out_kernel(float* __restrict__ out) {
    size_t idx = (size_t)blockIdx.x * 256 + threadIdx.x;
    ((float4*)out)[idx] = make_float4(0.f, 0.f, 0.f, 0.f);
}

// ===========================================================================
// GEMM2 hybrid (R10 config): M=64 x 128 h-cols. warps 0-3 mma (cols 0-63),
// warps 4-7 dp4a (cols 64-127). grid (64, E, 16). atomicAdd into out.
// ===========================================================================
#define ST2    15360
#define G2_META (3 * ST2)
#define G2_SMEM (G2_META + 1024)
#define NS2    22

__global__ __launch_bounds__(256, 2) void gemm2_mma(const float* __restrict__ s2_all,
                                                    float* __restrict__ out) {
    int e = blockIdx.y;
    int cnt = g_cnt[e];
    int m0 = blockIdx.x * 64;
    if (m0 >= cnt) return;
    int nt = min(64, cnt - m0);
    int z = blockIdx.z;

    extern __shared__ char smem[];
    uint32_t sb = smem_u32(smem);
    int* dst_s = (int*)(smem + G2_META);
    float* sc_s = (float*)(smem + G2_META + 256);
    int tid = threadIdx.x;

    if (tid < 64) {
        int packed; float gv;
        if (tid < nt) { packed = g_tok[e][m0 + tid]; gv = g_gate_arr[e][m0 + tid]; }
        else          { packed = g_tok[e][m0];       gv = 0.f; }
        dst_s[tid] = packed;
        sc_s[tid] = gv * g_sa[packed];
    }
    __syncthreads();

    const int8_t* w2 = g_w2 + (size_t)e * H_ * I_;
    int rA = tid >> 2, cA = (tid & 3) * 16;
    const int8_t* srcA = g_qact + (size_t)dst_s[rA] * I_ + cA;
    int rB = tid >> 1, cB = (tid & 1) * 32;
    const int8_t* srcB = w2 + (size_t)(z * 128 + rB) * I_ + cB;
    uint32_t dA = sb + rA * PAD + cA;
    uint32_t dB = sb + 5120 + rB * PAD + cB;

#pragma unroll
    for (int s = 0; s < 2; ++s) {
        CP16(dA + s * ST2, srcA + s * 64);
        CP16(dB + s * ST2, srcB + s * 64);
        CP16(dB + s * ST2 + 16, srcB + s * 64 + 16);
        CP_COMMIT();
    }

    int warp = tid >> 5, lane = tid & 31;

    if (warp < 4) {
        int wm = warp & 1, wv = warp >> 1;
        int sub = lane >> 2, q4 = (lane & 3) * 4;
        int acc[2][4][4];
#pragma unroll
        for (int mt = 0; mt < 2; ++mt)
#pragma unroll
            for (int n8 = 0; n8 < 4; ++n8)
#pragma unroll
                for (int r = 0; r < 4; ++r) acc[mt][n8][r] = 0;

        for (int ks = 0; ks < NS2; ++ks) {
            CP_WAIT1();
            __syncthreads();
            const char* As = smem + (ks % 3) * ST2;
            const char* Bs = As + 5120;
#pragma unroll
            for (int kk = 0; kk < 64; kk += 32) {
                uint32_t a[2][4];
#pragma unroll
                for (int mt = 0; mt < 2; ++mt) {
                    const char* ar = As + (wm * 32 + mt * 16 + sub) * PAD + kk + q4;
                    a[mt][0] = *(const uint32_t*)(ar);
                    a[mt][1] = *(const uint32_t*)(ar + 8 * PAD);
                    a[mt][2] = *(const uint32_t*)(ar + 16);
                    a[mt][3] = *(const uint32_t*)(ar + 8 * PAD + 16);
                }
#pragma unroll
                for (int n8 = 0; n8 < 4; ++n8) {
                    const char* br = Bs + (wv * 32 + n8 * 8 + sub) * PAD + kk + q4;
                    uint32_t b0 = *(const uint32_t*)(br);
                    uint32_t b1 = *(const uint32_t*)(br + 16);
#pragma unroll
                    for (int mt = 0; mt < 2; ++mt)
                        mma_s8(acc[mt][n8], a[mt][0], a[mt][1], a[mt][2], a[mt][3], b0, b1);
                }
            }
            if (ks + 2 < NS2) {
                int s = (ks + 2) % 3;
                int kb = (ks + 2) * 64;
                CP16(dA + s * ST2, srcA + kb);
                CP16(dB + s * ST2, srcB + kb);
                CP16(dB + s * ST2 + 16, srcB + kb + 16);
            }
            CP_COMMIT();
        }

        const float* s2w = s2_all + (size_t)e * H_ + z * 128;
#pragma unroll
        for (int mt = 0; mt < 2; ++mt) {
#pragma unroll
            for (int n8 = 0; n8 < 4; ++n8) {
                int col = wv * 32 + n8 * 8 + (lane & 3) * 2;
                float w0 = s2w[col], w1 = s2w[col + 1];
#pragma unroll
                for (int h2 = 0; h2 < 2; ++h2) {
                    int row = wm * 32 + mt * 16 + sub + h2 * 8;
                    if (row < nt) {
                        float sc = sc_s[row];
                        int t = dst_s[row] >> 1;
                        float* orow = out + (size_t)t * H_ + z * 128 + col;
                        atomicAdd(orow, (float)acc[mt][n8][h2 * 2 + 0] * sc * w0);
                        atomicAdd(orow + 1, (float)acc[mt][n8][h2 * 2 + 1] * sc * w1);
                    }
                }
            }
        }
    } else {
        int col = 64 + (warp - 4) * 16 + (lane & 15);
        int rg = lane >> 4;
        int acc[32];
#pragma unroll
        for (int r = 0; r < 32; ++r) acc[r] = 0;

        for (int ks = 0; ks < NS2; ++ks) {
            CP_WAIT1();
            __syncthreads();
            const char* As = smem + (ks % 3) * ST2;
            const char* Bs = As + 5120;
#pragma unroll
            for (int j = 0; j < 4; ++j) {
                int kk4 = ((rg * 2 + j) & 3) * 16;
                int4 bv = *(const int4*)(Bs + col * PAD + kk4);
#pragma unroll
                for (int r = 0; r < 32; ++r) {
                    int4 av = *(const int4*)(As + (rg * 32 + r) * PAD + kk4);
                    acc[r] = __dp4a(av.x, bv.x, acc[r]);
                    acc[r] = __dp4a(av.y, bv.y, acc[r]);
                    acc[r] = __dp4a(av.z, bv.z, acc[r]);
                    acc[r] = __dp4a(av.w, bv.w, acc[r]);
                }
            }
            if (ks + 2 < NS2) {
                int s = (ks + 2) % 3;
                int kb = (ks + 2) * 64;
                CP16(dA + s * ST2, srcA + kb);
                CP16(dB + s * ST2, srcB + kb);
                CP16(dB + s * ST2 + 16, srcB + kb + 16);
            }
            CP_COMMIT();
        }

        const float* s2w = s2_all + (size_t)e * H_ + z * 128;
        float w0 = s2w[col];
#pragma unroll
        for (int r = 0; r < 32; ++r) {
            int row = rg * 32 + r;
            if (row < nt) {
                float sc = sc_s[row];
                int t = dst_s[row] >> 1;
                atomicAdd(out + (size_t)t * H_ + z * 128 + col,
                          (float)acc[r] * sc * w0);
            }
        }
    }
}

// ---------------------------------------------------------------------------
extern "C" void kernel_launch(void* const* d_in, const int* in_sizes, int n_in,
                              void* d_out, int out_size) {
    const float* hid = nullptr;
    const float* gw = nullptr;
    const void* w13raw = nullptr;
    const float* s13 = nullptr;
    const void* w2raw = nullptr;
    const float* s2 = nullptr;
    for (int i = 0; i < n_in; ++i) {
        long long s = in_sizes[i];
        if (s == 8388608LL || s == 33554432LL) hid = (const float*)d_in[i];
        else if (s == 46137344LL || s == 184549376LL) w13raw = d_in[i];
        else if (s == 22528LL || s == 90112LL) s13 = (const float*)d_in[i];
        else if (s == 23068672LL || s == 92274688LL) w2raw = d_in[i];
        else if (s == 16384LL || s == 65536LL) {
            if (!gw) gw = (const float*)d_in[i];
            else s2 = (const float*)d_in[i];
        }
    }
    if (n_in >= 6) {
        if (!hid)    hid = (const float*)d_in[0];
        if (!gw)     gw = (const float*)d_in[1];
        if (!w13raw) w13raw = d_in[2];
        if (!s13)    s13 = (const float*)d_in[3];
        if (!w2raw)  w2raw = d_in[4];
        if (!s2)     s2 = (const float*)d_in[5];
    }
    float* out = (float*)d_out;

    cudaFuncSetAttribute(gemm1_mma, cudaFuncAttributeMaxDynamicSharedMemorySize, G1_SMEM);
    cudaFuncSetAttribute(gemm2_mma, cudaFuncAttributeMaxDynamicSharedMemorySize, G2_SMEM);

    convert_w13_kernel<<<8192, 256>>>(w13raw);            // 1
    convert_w2_kernel<<<8192, 256>>>(w2raw);              // 2
    gatequant_kernel<<<T_, 256>>>(hid, gw);               // 3
    dim3 g1(64, E_, 16);
    gemm1_mma<<<g1, 256, G1_SMEM>>>(s13);                 // 4 (profiled slot)
    requant_kernel<<<T_ * 2, 128>>>();                    // 5
    zero_out_kernel<<<(T_ * H_) / 1024, 256>>>(out);      // 6
    dim3 g2(64, E_, 16);
    gemm2_mma<<<g2, 256, G2_SMEM>>>(s2, out);             // 7
}

// round 14
// speedup vs baseline: 1.0546x; 1.0451x over previous
#include <cuda_runtime.h>
#include <cstdint>
#include <math.h>

#define T_    4096
#define H_    2048
#define I_    1408
#define E_    8
#define TWOI  2816

// ---------------- scratch ----------------
__device__ int8_t g_qin[(size_t)T_ * H_];
__device__ float  g_sin[T_];
__device__ int    g_cnt[E_];
__device__ int    g_tok[E_][T_];
__device__ float  g_gate_arr[E_][T_];
__device__ int8_t g_w13[(size_t)E_ * TWOI * H_];
__device__ int8_t g_w2[(size_t)E_ * H_ * I_];
__device__ float  g_act[(size_t)T_ * 2 * I_];
__device__ int8_t g_qact[(size_t)T_ * 2 * I_];
__device__ float  g_sa[T_ * 2];

// ---------------- helpers ----------------
__device__ __forceinline__ uint32_t smem_u32(const void* p) {
    uint32_t a;
    asm("{ .reg .u64 t; cvta.to.shared.u64 t, %1; cvt.u32.u64 %0, t; }" : "=r"(a) : "l"(p));
    return a;
}
#define CP16(dst, src) asm volatile("cp.async.cg.shared.global [%0], [%1], 16;" :: "r"(dst), "l"(src))
#define CP_COMMIT()    asm volatile("cp.async.commit_group;" ::: "memory")
#define CP_WAIT1()     asm volatile("cp.async.wait_group 1;" ::: "memory")

__device__ __forceinline__ void mma_s8(int* d, uint32_t a0, uint32_t a1, uint32_t a2, uint32_t a3,
                                       uint32_t b0, uint32_t b1) {
    asm volatile("mma.sync.aligned.m16n8k32.row.col.s32.s8.s8.s32 "
                 "{%0,%1,%2,%3}, {%4,%5,%6,%7}, {%8,%9}, {%0,%1,%2,%3};"
                 : "+r"(d[0]), "+r"(d[1]), "+r"(d[2]), "+r"(d[3])
                 : "r"(a0), "r"(a1), "r"(a2), "r"(a3), "r"(b0), "r"(b1));
}

// ---------------- weight conversion ----------------
__device__ __forceinline__ char4 conv_elem(const void* __restrict__ src, int idx, int mode) {
    if (mode == 1) {
        int4 v = ((const int4*)src)[idx];
        return make_char4((signed char)v.x, (signed char)v.y, (signed char)v.z, (signed char)v.w);
    } else if (mode == 2) {
        float4 v = ((const float4*)src)[idx];
        return make_char4((signed char)(int)v.x, (signed char)(int)v.y,
                          (signed char)(int)v.z, (signed char)(int)v.w);
    }
    return ((const char4*)src)[idx];
}
__device__ __forceinline__ int block_detect_mode(const void* src) {
    int tid = threadIdx.x;
    int v = ((const int*)src)[tid];
    float f = ((const float*)src)[tid];
    int n32 = __syncthreads_count(v >= -127 && v <= 127);
    int nf = __syncthreads_count(fabsf(f) <= 127.f && rintf(f) == f);
    return (n32 >= 250) ? 1 : ((nf >= 250) ? 2 : 0);
}
#define N4_W13 ((E_ * TWOI * H_) / 4)
#define N4_W2  ((E_ * H_ * I_) / 4)

__global__ __launch_bounds__(256) void convert_w13_kernel(const void* __restrict__ src) {
    int mode = block_detect_mode(src);
    for (int idx = blockIdx.x * 256 + threadIdx.x; idx < N4_W13; idx += gridDim.x * 256)
        ((char4*)g_w13)[idx] = conv_elem(src, idx, mode);
    if (blockIdx.x == 0 && threadIdx.x < E_) g_cnt[threadIdx.x] = 0;
}
__global__ __launch_bounds__(256) void convert_w2_kernel(const void* __restrict__ src) {
    int mode = block_detect_mode(src);
    for (int idx = blockIdx.x * 256 + threadIdx.x; idx < N4_W2; idx += gridDim.x * 256)
        ((char4*)g_w2)[idx] = conv_elem(src, idx, mode);
}

// ---------------- gate + quantize ----------------
__global__ __launch_bounds__(256) void gatequant_kernel(const float* __restrict__ hid,
                                                        const float* __restrict__ gw) {
    int t = blockIdx.x;
    const float* x = hid + (size_t)t * H_;
    float part[E_];
#pragma unroll
    for (int e = 0; e < E_; ++e) part[e] = 0.f;
    float amax = 0.f;
    for (int j = threadIdx.x; j < H_; j += 256) {
        float v = x[j];
        amax = fmaxf(amax, fabsf(v));
#pragma unroll
        for (int e = 0; e < E_; ++e) part[e] = fmaf(v, gw[e * H_ + j], part[e]);
    }
#pragma unroll
    for (int off = 16; off; off >>= 1) {
        amax = fmaxf(amax, __shfl_down_sync(0xffffffffu, amax, off));
#pragma unroll
        for (int e = 0; e < E_; ++e) part[e] += __shfl_down_sync(0xffffffffu, part[e], off);
    }
    __shared__ float red[8][E_ + 1];
    __shared__ float s_sh;
    int warp = threadIdx.x >> 5, lane = threadIdx.x & 31;
    if (lane == 0) {
#pragma unroll
        for (int e = 0; e < E_; ++e) red[warp][e] = part[e];
        red[warp][E_] = amax;
    }
    __syncthreads();
    if (threadIdx.x == 0) {
        float l[E_]; float am = 0.f;
#pragma unroll
        for (int e = 0; e < E_; ++e) l[e] = 0.f;
        for (int w = 0; w < 8; ++w) {
#pragma unroll
            for (int e = 0; e < E_; ++e) l[e] += red[w][e];
            am = fmaxf(am, red[w][E_]);
        }
        float b1 = -1e30f, b2 = -1e30f; int i1 = 0, i2 = 0;
#pragma unroll
        for (int e = 0; e < E_; ++e) {
            float v = l[e];
            if (v > b1) { b2 = b1; i2 = i1; b1 = v; i1 = e; }
            else if (v > b2) { b2 = v; i2 = e; }
        }
        float e2v = expf(b2 - b1);
        float inv = __fdiv_rn(1.f, 1.f + e2v);
        float s = fmaxf(__fdiv_rn(am, 127.f), 1e-8f);
        g_sin[t] = s; s_sh = s;
        int p0 = atomicAdd(&g_cnt[i1], 1);
        g_tok[i1][p0] = t * 2 + 0; g_gate_arr[i1][p0] = inv;
        int p1 = atomicAdd(&g_cnt[i2], 1);
        g_tok[i2][p1] = t * 2 + 1; g_gate_arr[i2][p1] = e2v * inv;
    }
    __syncthreads();
    float s = s_sh;
    const float4* xv = (const float4*)x;
    char4* q = (char4*)(g_qin + (size_t)t * H_);
    for (int j = threadIdx.x; j < H_ / 4; j += 256) {
        float4 v = xv[j];
        float a = fminf(fmaxf(rintf(__fdiv_rn(v.x, s)), -127.f), 127.f);
        float b = fminf(fmaxf(rintf(__fdiv_rn(v.y, s)), -127.f), 127.f);
        float c = fminf(fmaxf(rintf(__fdiv_rn(v.z, s)), -127.f), 127.f);
        float d = fminf(fmaxf(rintf(__fdiv_rn(v.w, s)), -127.f), 127.f);
        q[j] = make_char4((signed char)a, (signed char)b, (signed char)c, (signed char)d);
    }
}

// ===========================================================================
// GEMM1 hybrid (R10 layout, occ 3): M=64 x 64 i-cols. warps 0-3 mma
// (cols 0-31), warps 4-7 dp4a (cols 32-63). 3-stage cp.async. grid (64,E,22).
// ===========================================================================
#define PAD    80
#define ST1    15360
#define G1_META (3 * ST1)
#define G1_SMEM (G1_META + 768)
#define NS1    32

__global__ __launch_bounds__(256, 3) void gemm1_mma(const float* __restrict__ s13_all) {
    int e = blockIdx.y;
    int cnt = g_cnt[e];
    int m0 = blockIdx.x * 64;
    if (m0 >= cnt) return;
    int nt = min(64, cnt - m0);
    int z = blockIdx.z;

    extern __shared__ char smem[];
    uint32_t sb = smem_u32(smem);
    int* dst_s = (int*)(smem + G1_META);
    float* sin_s = (float*)(smem + G1_META + 256);
    int tid = threadIdx.x;

    if (tid < 64) {
        int packed = (tid < nt) ? g_tok[e][m0 + tid] : g_tok[e][m0];
        dst_s[tid] = packed;
        sin_s[tid] = g_sin[packed >> 1];
    }
    __syncthreads();

    const int8_t* w13 = g_w13 + (size_t)e * TWOI * H_;
    int rA = tid >> 2, cA = (tid & 3) * 16;
    const int8_t* srcA = g_qin + (size_t)(dst_s[rA] >> 1) * H_ + cA;
    int rB = tid >> 1, cB = (tid & 1) * 32;
    const int8_t* srcB = (rB < 64)
        ? w13 + (size_t)(z * 64 + rB) * H_ + cB
        : w13 + (size_t)(I_ + z * 64 + (rB - 64)) * H_ + cB;
    uint32_t dA = sb + rA * PAD + cA;
    uint32_t dB = sb + 5120 + rB * PAD + cB;

#pragma unroll
    for (int s = 0; s < 2; ++s) {
        CP16(dA + s * ST1, srcA + s * 64);
        CP16(dB + s * ST1, srcB + s * 64);
        CP16(dB + s * ST1 + 16, srcB + s * 64 + 16);
        CP_COMMIT();
    }

    int warp = tid >> 5, lane = tid & 31;

    if (warp < 4) {
        // ---- mma role: i-cols [0,32) ----
        int wm = warp & 1, wn = warp >> 1;
        int sub = lane >> 2, q4 = (lane & 3) * 4;
        int accg[2][2][4], accu[2][2][4];
#pragma unroll
        for (int mt = 0; mt < 2; ++mt)
#pragma unroll
            for (int n8 = 0; n8 < 2; ++n8)
#pragma unroll
                for (int r = 0; r < 4; ++r) { accg[mt][n8][r] = 0; accu[mt][n8][r] = 0; }

        for (int ks = 0; ks < NS1; ++ks) {
            CP_WAIT1();
            __syncthreads();
            const char* As = smem + (ks % 3) * ST1;
            const char* Bs = As + 5120;
#pragma unroll
            for (int kk = 0; kk < 64; kk += 32) {
                uint32_t a[2][4];
#pragma unroll
                for (int mt = 0; mt < 2; ++mt) {
                    const char* ar = As + (wm * 32 + mt * 16 + sub) * PAD + kk + q4;
                    a[mt][0] = *(const uint32_t*)(ar);
                    a[mt][1] = *(const uint32_t*)(ar + 8 * PAD);
                    a[mt][2] = *(const uint32_t*)(ar + 16);
                    a[mt][3] = *(const uint32_t*)(ar + 8 * PAD + 16);
                }
#pragma unroll
                for (int n8 = 0; n8 < 2; ++n8) {
                    const char* bg = Bs + (wn * 16 + n8 * 8 + sub) * PAD + kk + q4;
                    uint32_t g0 = *(const uint32_t*)(bg);
                    uint32_t g1 = *(const uint32_t*)(bg + 16);
                    uint32_t u0 = *(const uint32_t*)(bg + 64 * PAD);
                    uint32_t u1 = *(const uint32_t*)(bg + 64 * PAD + 16);
#pragma unroll
                    for (int mt = 0; mt < 2; ++mt) {
                        mma_s8(accg[mt][n8], a[mt][0], a[mt][1], a[mt][2], a[mt][3], g0, g1);
                        mma_s8(accu[mt][n8], a[mt][0], a[mt][1], a[mt][2], a[mt][3], u0, u1);
                    }
                }
            }
            if (ks + 2 < NS1) {
                int s = (ks + 2) % 3;
                int kb = (ks + 2) * 64;
                CP16(dA + s * ST1, srcA + kb);
                CP16(dB + s * ST1, srcB + kb);
                CP16(dB + s * ST1 + 16, srcB + kb + 16);
            }
            CP_COMMIT();
        }

        const float* s13 = s13_all + (size_t)e * TWOI + z * 64;
#pragma unroll
        for (int mt = 0; mt < 2; ++mt) {
#pragma unroll
            for (int n8 = 0; n8 < 2; ++n8) {
                int col = wn * 16 + n8 * 8 + (lane & 3) * 2;
                float sg0 = s13[col], sg1 = s13[col + 1];
                float su0 = s13[col + I_], su1 = s13[col + I_ + 1];
#pragma unroll
                for (int h2 = 0; h2 < 2; ++h2) {
                    int row = wm * 32 + mt * 16 + sub + h2 * 8;
                    if (row < nt) {
                        float si = sin_s[row];
                        float g0 = (float)accg[mt][n8][h2 * 2 + 0] * si * sg0;
                        float g1 = (float)accg[mt][n8][h2 * 2 + 1] * si * sg1;
                        float u0 = (float)accu[mt][n8][h2 * 2 + 0] * si * su0;
                        float u1 = (float)accu[mt][n8][h2 * 2 + 1] * si * su1;
                        float a0 = g0 * __fdiv_rn(1.f, 1.f + expf(-g0)) * u0;
                        float a1 = g1 * __fdiv_rn(1.f, 1.f + expf(-g1)) * u1;
                        *(float2*)(g_act + (size_t)dst_s[row] * I_ + z * 64 + col) =
                            make_float2(a0, a1);
                    }
                }
            }
        }
    } else {
        // ---- dp4a role: i-cols [32,64) ----
        int col = 32 + (warp - 4) * 8 + (lane & 7);
        int rg = lane >> 3;
        int accg[16], accu[16];
#pragma unroll
        for (int r = 0; r < 16; ++r) { accg[r] = 0; accu[r] = 0; }

        for (int ks = 0; ks < NS1; ++ks) {
            CP_WAIT1();
            __syncthreads();
            const char* As = smem + (ks % 3) * ST1;
            const char* Bs = As + 5120;
#pragma unroll
            for (int j = 0; j < 4; ++j) {
                int kk4 = ((rg + j) & 3) * 16;
                int4 bg = *(const int4*)(Bs + col * PAD + kk4);
                int4 bu = *(const int4*)(Bs + (64 + col) * PAD + kk4);
#pragma unroll
                for (int r = 0; r < 16; ++r) {
                    int4 av = *(const int4*)(As + (rg * 16 + r) * PAD + kk4);
                    accg[r] = __dp4a(av.x, bg.x, accg[r]);
                    accg[r] = __dp4a(av.y, bg.y, accg[r]);
                    accg[r] = __dp4a(av.z, bg.z, accg[r]);
                    accg[r] = __dp4a(av.w, bg.w, accg[r]);
                    accu[r] = __dp4a(av.x, bu.x, accu[r]);
                    accu[r] = __dp4a(av.y, bu.y, accu[r]);
                    accu[r] = __dp4a(av.z, bu.z, accu[r]);
                    accu[r] = __dp4a(av.w, bu.w, accu[r]);
                }
            }
            if (ks + 2 < NS1) {
                int s = (ks + 2) % 3;
                int kb = (ks + 2) * 64;
                CP16(dA + s * ST1, srcA + kb);
                CP16(dB + s * ST1, srcB + kb);
                CP16(dB + s * ST1 + 16, srcB + kb + 16);
            }
            CP_COMMIT();
        }

        const float* s13 = s13_all + (size_t)e * TWOI + z * 64;
        float sg = s13[col], su = s13[col + I_];
#pragma unroll
        for (int r = 0; r < 16; ++r) {
            int row = rg * 16 + r;
            if (row < nt) {
                float si = sin_s[row];
                float g = (float)accg[r] * si * sg;
                float u = (float)accu[r] * si * su;
                g_act[(size_t)dst_s[row] * I_ + z * 64 + col] =
                    g * __fdiv_rn(1.f, 1.f + expf(-g)) * u;
            }
        }
    }
}

// ---------------- requant ----------------
__global__ __launch_bounds__(128) void requant_kernel() {
    int dst = blockIdx.x;
    const float* a = g_act + (size_t)dst * I_;
    int tid = threadIdx.x;
    float m = 0.f;
    for (int i = tid; i < I_; i += 128) m = fmaxf(m, fabsf(a[i]));
    __shared__ float red[4];
#pragma unroll
    for (int off = 16; off; off >>= 1) m = fmaxf(m, __shfl_down_sync(0xffffffffu, m, off));
    if ((tid & 31) == 0) red[tid >> 5] = m;
    __syncthreads();
    float mm = fmaxf(fmaxf(red[0], red[1]), fmaxf(red[2], red[3]));
    float sa = fmaxf(__fdiv_rn(mm, 127.f), 1e-8f);
    if (tid == 0) g_sa[dst] = sa;
    int8_t* q = g_qact + (size_t)dst * I_;
    for (int i = tid; i < I_; i += 128) {
        float v = fminf(fmaxf(rintf(__fdiv_rn(a[i], sa)), -127.f), 127.f);
        q[i] = (int8_t)v;
    }
}

// ---------------- zero output ----------------
__global__ __launch_bounds__(256) void zero_out_kernel(float* __restrict__ out) {
    size_t idx = (size_t)blockIdx.x * 256 + threadIdx.x;
    ((float4*)out)[idx] = make_float4(0.f, 0.f, 0.f, 0.f);
}

// ===========================================================================
// GEMM2 hybrid (R10 layout, occ 3): M=64 x 128 h-cols. warps 0-3 mma
// (cols 0-63), warps 4-7 dp4a (cols 64-127). grid (64,E,16). atomicAdd out.
// ===========================================================================
#define ST2    15360
#define G2_META (3 * ST2)
#define G2_SMEM (G2_META + 1024)
#define NS2    22

__global__ __launch_bounds__(256, 3) void gemm2_mma(const float* __restrict__ s2_all,
                                                    float* __restrict__ out) {
    int e = blockIdx.y;
    int cnt = g_cnt[e];
    int m0 = blockIdx.x * 64;
    if (m0 >= cnt) return;
    int nt = min(64, cnt - m0);
    int z = blockIdx.z;

    extern __shared__ char smem[];
    uint32_t sb = smem_u32(smem);
    int* dst_s = (int*)(smem + G2_META);
    float* sc_s = (float*)(smem + G2_META + 256);
    int tid = threadIdx.x;

    if (tid < 64) {
        int packed; float gv;
        if (tid < nt) { packed = g_tok[e][m0 + tid]; gv = g_gate_arr[e][m0 + tid]; }
        else          { packed = g_tok[e][m0];       gv = 0.f; }
        dst_s[tid] = packed;
        sc_s[tid] = gv * g_sa[packed];
    }
    __syncthreads();

    const int8_t* w2 = g_w2 + (size_t)e * H_ * I_;
    int rA = tid >> 2, cA = (tid & 3) * 16;
    const int8_t* srcA = g_qact + (size_t)dst_s[rA] * I_ + cA;
    int rB = tid >> 1, cB = (tid & 1) * 32;
    const int8_t* srcB = w2 + (size_t)(z * 128 + rB) * I_ + cB;
    uint32_t dA = sb + rA * PAD + cA;
    uint32_t dB = sb + 5120 + rB * PAD + cB;

#pragma unroll
    for (int s = 0; s < 2; ++s) {
        CP16(dA + s * ST2, srcA + s * 64);
        CP16(dB + s * ST2, srcB + s * 64);
        CP16(dB + s * ST2 + 16, srcB + s * 64 + 16);
        CP_COMMIT();
    }

    int warp = tid >> 5, lane = tid & 31;

    if (warp < 4) {
        int wm = warp & 1, wv = warp >> 1;
        int sub = lane >> 2, q4 = (lane & 3) * 4;
        int acc[2][4][4];
#pragma unroll
        for (int mt = 0; mt < 2; ++mt)
#pragma unroll
            for (int n8 = 0; n8 < 4; ++n8)
#pragma unroll
                for (int r = 0; r < 4; ++r) acc[mt][n8][r] = 0;

        for (int ks = 0; ks < NS2; ++ks) {
            CP_WAIT1();
            __syncthreads();
            const char* As = smem + (ks % 3) * ST2;
            const char* Bs = As + 5120;
#pragma unroll
            for (int kk = 0; kk < 64; kk += 32) {
                uint32_t a[2][4];
#pragma unroll
                for (int mt = 0; mt < 2; ++mt) {
                    const char* ar = As + (wm * 32 + mt * 16 + sub) * PAD + kk + q4;
                    a[mt][0] = *(const uint32_t*)(ar);
                    a[mt][1] = *(const uint32_t*)(ar + 8 * PAD);
                    a[mt][2] = *(const uint32_t*)(ar + 16);
                    a[mt][3] = *(const uint32_t*)(ar + 8 * PAD + 16);
                }
#pragma unroll
                for (int n8 = 0; n8 < 4; ++n8) {
                    const char* br = Bs + (wv * 32 + n8 * 8 + sub) * PAD + kk + q4;
                    uint32_t b0 = *(const uint32_t*)(br);
                    uint32_t b1 = *(const uint32_t*)(br + 16);
#pragma unroll
                    for (int mt = 0; mt < 2; ++mt)
                        mma_s8(acc[mt][n8], a[mt][0], a[mt][1], a[mt][2], a[mt][3], b0, b1);
                }
            }
            if (ks + 2 < NS2) {
                int s = (ks + 2) % 3;
                int kb = (ks + 2) * 64;
                CP16(dA + s * ST2, srcA + kb);
                CP16(dB + s * ST2, srcB + kb);
                CP16(dB + s * ST2 + 16, srcB + kb + 16);
            }
            CP_COMMIT();
        }

        const float* s2w = s2_all + (size_t)e * H_ + z * 128;
#pragma unroll
        for (int mt = 0; mt < 2; ++mt) {
#pragma unroll
            for (int n8 = 0; n8 < 4; ++n8) {
                int col = wv * 32 + n8 * 8 + (lane & 3) * 2;
                float w0 = s2w[col], w1 = s2w[col + 1];
#pragma unroll
                for (int h2 = 0; h2 < 2; ++h2) {
                    int row = wm * 32 + mt * 16 + sub + h2 * 8;
                    if (row < nt) {
                        float sc = sc_s[row];
                        int t = dst_s[row] >> 1;
                        float* orow = out + (size_t)t * H_ + z * 128 + col;
                        atomicAdd(orow, (float)acc[mt][n8][h2 * 2 + 0] * sc * w0);
                        atomicAdd(orow + 1, (float)acc[mt][n8][h2 * 2 + 1] * sc * w1);
                    }
                }
            }
        }
    } else {
        int col = 64 + (warp - 4) * 16 + (lane & 15);
        int rg = lane >> 4;
        int acc[32];
#pragma unroll
        for (int r = 0; r < 32; ++r) acc[r] = 0;

        for (int ks = 0; ks < NS2; ++ks) {
            CP_WAIT1();
            __syncthreads();
            const char* As = smem + (ks % 3) * ST2;
            const char* Bs = As + 5120;
#pragma unroll
            for (int j = 0; j < 4; ++j) {
                int kk4 = ((rg * 2 + j) & 3) * 16;
                int4 bv = *(const int4*)(Bs + col * PAD + kk4);
#pragma unroll
                for (int r = 0; r < 32; ++r) {
                    int4 av = *(const int4*)(As + (rg * 32 + r) * PAD + kk4);
                    acc[r] = __dp4a(av.x, bv.x, acc[r]);
                    acc[r] = __dp4a(av.y, bv.y, acc[r]);
                    acc[r] = __dp4a(av.z, bv.z, acc[r]);
                    acc[r] = __dp4a(av.w, bv.w, acc[r]);
                }
            }
            if (ks + 2 < NS2) {
                int s = (ks + 2) % 3;
                int kb = (ks + 2) * 64;
                CP16(dA + s * ST2, srcA + kb);
                CP16(dB + s * ST2, srcB + kb);
                CP16(dB + s * ST2 + 16, srcB + kb + 16);
            }
            CP_COMMIT();
        }

        const float* s2w = s2_all + (size_t)e * H_ + z * 128;
        float w0 = s2w[col];
#pragma unroll
        for (int r = 0; r < 32; ++r) {
            int row = rg * 32 + r;
            if (row < nt) {
                float sc = sc_s[row];
                int t = dst_s[row] >> 1;
                atomicAdd(out + (size_t)t * H_ + z * 128 + col,
                          (float)acc[r] * sc * w0);
            }
        }
    }
}

// ---------------------------------------------------------------------------
extern "C" void kernel_launch(void* const* d_in, const int* in_sizes, int n_in,
                              void* d_out, int out_size) {
    const float* hid = nullptr;
    const float* gw = nullptr;
    const void* w13raw = nullptr;
    const float* s13 = nullptr;
    const void* w2raw = nullptr;
    const float* s2 = nullptr;
    for (int i = 0; i < n_in; ++i) {
        long long s = in_sizes[i];
        if (s == 8388608LL || s == 33554432LL) hid = (const float*)d_in[i];
        else if (s == 46137344LL || s == 184549376LL) w13raw = d_in[i];
        else if (s == 22528LL || s == 90112LL) s13 = (const float*)d_in[i];
        else if (s == 23068672LL || s == 92274688LL) w2raw = d_in[i];
        else if (s == 16384LL || s == 65536LL) {
            if (!gw) gw = (const float*)d_in[i];
            else s2 = (const float*)d_in[i];
        }
    }
    if (n_in >= 6) {
        if (!hid)    hid = (const float*)d_in[0];
        if (!gw)     gw = (const float*)d_in[1];
        if (!w13raw) w13raw = d_in[2];
        if (!s13)    s13 = (const float*)d_in[3];
        if (!w2raw)  w2raw = d_in[4];
        if (!s2)     s2 = (const float*)d_in[5];
    }
    float* out = (float*)d_out;

    cudaFuncSetAttribute(gemm1_mma, cudaFuncAttributeMaxDynamicSharedMemorySize, G1_SMEM);
    cudaFuncSetAttribute(gemm2_mma, cudaFuncAttributeMaxDynamicSharedMemorySize, G2_SMEM);

    convert_w13_kernel<<<8192, 256>>>(w13raw);            // 1
    convert_w2_kernel<<<8192, 256>>>(w2raw);              // 2
    gatequant_kernel<<<T_, 256>>>(hid, gw);               // 3
    dim3 g1(64, E_, 22);
    gemm1_mma<<<g1, 256, G1_SMEM>>>(s13);                 // 4 (profiled slot)
    requant_kernel<<<T_ * 2, 128>>>();                    // 5
    zero_out_kernel<<<(T_ * H_) / 1024, 256>>>(out);      // 6
    dim3 g2(64, E_, 16);
    gemm2_mma<<<g2, 256, G2_SMEM>>>(s2, out);             // 7
}

// round 15
// speedup vs baseline: 1.0805x; 1.0245x over previous
#include <cuda_runtime.h>
#include <cstdint>
#include <math.h>

#define T_    4096
#define H_    2048
#define I_    1408
#define E_    8
#define TWOI  2816

// ---------------- scratch ----------------
__device__ int8_t g_qin[(size_t)T_ * H_];
__device__ float  g_sin[T_];
__device__ int    g_cnt[E_];
__device__ int    g_tok[E_][T_];
__device__ float  g_gate_arr[E_][T_];
__device__ int8_t g_w13[(size_t)E_ * TWOI * H_];
__device__ int8_t g_w2[(size_t)E_ * H_ * I_];
__device__ float  g_act[(size_t)T_ * 2 * I_];
__device__ int8_t g_qact[(size_t)T_ * 2 * I_];
__device__ float  g_sa[T_ * 2];

// ---------------- helpers ----------------
__device__ __forceinline__ uint32_t smem_u32(const void* p) {
    uint32_t a;
    asm("{ .reg .u64 t; cvta.to.shared.u64 t, %1; cvt.u32.u64 %0, t; }" : "=r"(a) : "l"(p));
    return a;
}
#define CP16(dst, src) asm volatile("cp.async.cg.shared.global [%0], [%1], 16;" :: "r"(dst), "l"(src))
#define CP_COMMIT()    asm volatile("cp.async.commit_group;" ::: "memory")
#define CP_WAIT1()     asm volatile("cp.async.wait_group 1;" ::: "memory")

__device__ __forceinline__ void mma_s8(int* d, uint32_t a0, uint32_t a1, uint32_t a2, uint32_t a3,
                                       uint32_t b0, uint32_t b1) {
    asm volatile("mma.sync.aligned.m16n8k32.row.col.s32.s8.s8.s32 "
                 "{%0,%1,%2,%3}, {%4,%5,%6,%7}, {%8,%9}, {%0,%1,%2,%3};"
                 : "+r"(d[0]), "+r"(d[1]), "+r"(d[2]), "+r"(d[3])
                 : "r"(a0), "r"(a1), "r"(a2), "r"(a3), "r"(b0), "r"(b1));
}

// ---------------- weight conversion (single merged launch) ----------------
__device__ __forceinline__ char4 conv_elem(const void* __restrict__ src, int idx, int mode) {
    if (mode == 1) {
        int4 v = ((const int4*)src)[idx];
        return make_char4((signed char)v.x, (signed char)v.y, (signed char)v.z, (signed char)v.w);
    } else if (mode == 2) {
        float4 v = ((const float4*)src)[idx];
        return make_char4((signed char)(int)v.x, (signed char)(int)v.y,
                          (signed char)(int)v.z, (signed char)(int)v.w);
    }
    return ((const char4*)src)[idx];
}
#define N4_W13 ((E_ * TWOI * H_) / 4)
#define N4_W2  ((E_ * H_ * I_) / 4)

__global__ __launch_bounds__(256) void convert_all_kernel(const void* __restrict__ src13,
                                                          const void* __restrict__ src2) {
    // block-local dtype detect from w13 header
    int tid = threadIdx.x;
    int v = ((const int*)src13)[tid];
    float f = ((const float*)src13)[tid];
    int n32 = __syncthreads_count(v >= -127 && v <= 127);
    int nf = __syncthreads_count(fabsf(f) <= 127.f && rintf(f) == f);
    int mode = (n32 >= 250) ? 1 : ((nf >= 250) ? 2 : 0);

    int stride = gridDim.x * 256;
    for (int idx = blockIdx.x * 256 + tid; idx < N4_W13; idx += stride)
        ((char4*)g_w13)[idx] = conv_elem(src13, idx, mode);
    for (int idx = blockIdx.x * 256 + tid; idx < N4_W2; idx += stride)
        ((char4*)g_w2)[idx] = conv_elem(src2, idx, mode);
    if (blockIdx.x == 0 && tid < E_) g_cnt[tid] = 0;
}

// ---------------- gate + quantize ----------------
__global__ __launch_bounds__(256) void gatequant_kernel(const float* __restrict__ hid,
                                                        const float* __restrict__ gw) {
    int t = blockIdx.x;
    const float* x = hid + (size_t)t * H_;
    float part[E_];
#pragma unroll
    for (int e = 0; e < E_; ++e) part[e] = 0.f;
    float amax = 0.f;
    for (int j = threadIdx.x; j < H_; j += 256) {
        float v = x[j];
        amax = fmaxf(amax, fabsf(v));
#pragma unroll
        for (int e = 0; e < E_; ++e) part[e] = fmaf(v, gw[e * H_ + j], part[e]);
    }
#pragma unroll
    for (int off = 16; off; off >>= 1) {
        amax = fmaxf(amax, __shfl_down_sync(0xffffffffu, amax, off));
#pragma unroll
        for (int e = 0; e < E_; ++e) part[e] += __shfl_down_sync(0xffffffffu, part[e], off);
    }
    __shared__ float red[8][E_ + 1];
    __shared__ float s_sh;
    int warp = threadIdx.x >> 5, lane = threadIdx.x & 31;
    if (lane == 0) {
#pragma unroll
        for (int e = 0; e < E_; ++e) red[warp][e] = part[e];
        red[warp][E_] = amax;
    }
    __syncthreads();
    if (threadIdx.x == 0) {
        float l[E_]; float am = 0.f;
#pragma unroll
        for (int e = 0; e < E_; ++e) l[e] = 0.f;
        for (int w = 0; w < 8; ++w) {
#pragma unroll
            for (int e = 0; e < E_; ++e) l[e] += red[w][e];
            am = fmaxf(am, red[w][E_]);
        }
        float b1 = -1e30f, b2 = -1e30f; int i1 = 0, i2 = 0;
#pragma unroll
        for (int e = 0; e < E_; ++e) {
            float v = l[e];
            if (v > b1) { b2 = b1; i2 = i1; b1 = v; i1 = e; }
            else if (v > b2) { b2 = v; i2 = e; }
        }
        float e2v = expf(b2 - b1);
        float inv = __fdiv_rn(1.f, 1.f + e2v);
        float s = fmaxf(__fdiv_rn(am, 127.f), 1e-8f);
        g_sin[t] = s; s_sh = s;
        int p0 = atomicAdd(&g_cnt[i1], 1);
        g_tok[i1][p0] = t * 2 + 0; g_gate_arr[i1][p0] = inv;
        int p1 = atomicAdd(&g_cnt[i2], 1);
        g_tok[i2][p1] = t * 2 + 1; g_gate_arr[i2][p1] = e2v * inv;
    }
    __syncthreads();
    float s = s_sh;
    const float4* xv = (const float4*)x;
    char4* q = (char4*)(g_qin + (size_t)t * H_);
    for (int j = threadIdx.x; j < H_ / 4; j += 256) {
        float4 v = xv[j];
        float a = fminf(fmaxf(rintf(__fdiv_rn(v.x, s)), -127.f), 127.f);
        float b = fminf(fmaxf(rintf(__fdiv_rn(v.y, s)), -127.f), 127.f);
        float c = fminf(fmaxf(rintf(__fdiv_rn(v.z, s)), -127.f), 127.f);
        float d = fminf(fmaxf(rintf(__fdiv_rn(v.w, s)), -127.f), 127.f);
        q[j] = make_char4((signed char)a, (signed char)b, (signed char)c, (signed char)d);
    }
}

// ===========================================================================
// GEMM1 hybrid (R10 config): M=64 x 64 i-cols. warps 0-3 mma (cols 0-31),
// warps 4-7 dp4a (cols 32-63). 3-stage cp.async. grid (64, E, 22).
// ===========================================================================
#define PAD    80
#define ST1    15360
#define G1_META (3 * ST1)
#define G1_SMEM (G1_META + 768)
#define NS1    32

__global__ __launch_bounds__(256, 2) void gemm1_mma(const float* __restrict__ s13_all) {
    int e = blockIdx.y;
    int cnt = g_cnt[e];
    int m0 = blockIdx.x * 64;
    if (m0 >= cnt) return;
    int nt = min(64, cnt - m0);
    int z = blockIdx.z;

    extern __shared__ char smem[];
    uint32_t sb = smem_u32(smem);
    int* dst_s = (int*)(smem + G1_META);
    float* sin_s = (float*)(smem + G1_META + 256);
    int tid = threadIdx.x;

    if (tid < 64) {
        int packed = (tid < nt) ? g_tok[e][m0 + tid] : g_tok[e][m0];
        dst_s[tid] = packed;
        sin_s[tid] = g_sin[packed >> 1];
    }
    __syncthreads();

    const int8_t* w13 = g_w13 + (size_t)e * TWOI * H_;
    int rA = tid >> 2, cA = (tid & 3) * 16;
    const int8_t* srcA = g_qin + (size_t)(dst_s[rA] >> 1) * H_ + cA;
    int rB = tid >> 1, cB = (tid & 1) * 32;
    const int8_t* srcB = (rB < 64)
        ? w13 + (size_t)(z * 64 + rB) * H_ + cB
        : w13 + (size_t)(I_ + z * 64 + (rB - 64)) * H_ + cB;
    uint32_t dA = sb + rA * PAD + cA;
    uint32_t dB = sb + 5120 + rB * PAD + cB;

#pragma unroll
    for (int s = 0; s < 2; ++s) {
        CP16(dA + s * ST1, srcA + s * 64);
        CP16(dB + s * ST1, srcB + s * 64);
        CP16(dB + s * ST1 + 16, srcB + s * 64 + 16);
        CP_COMMIT();
    }

    int warp = tid >> 5, lane = tid & 31;

    if (warp < 4) {
        // ---- mma role: i-cols [0,32) ----
        int wm = warp & 1, wn = warp >> 1;
        int sub = lane >> 2, q4 = (lane & 3) * 4;
        int accg[2][2][4], accu[2][2][4];
#pragma unroll
        for (int mt = 0; mt < 2; ++mt)
#pragma unroll
            for (int n8 = 0; n8 < 2; ++n8)
#pragma unroll
                for (int r = 0; r < 4; ++r) { accg[mt][n8][r] = 0; accu[mt][n8][r] = 0; }

        for (int ks = 0; ks < NS1; ++ks) {
            CP_WAIT1();
            __syncthreads();
            const char* As = smem + (ks % 3) * ST1;
            const char* Bs = As + 5120;
#pragma unroll
            for (int kk = 0; kk < 64; kk += 32) {
                uint32_t a[2][4];
#pragma unroll
                for (int mt = 0; mt < 2; ++mt) {
                    const char* ar = As + (wm * 32 + mt * 16 + sub) * PAD + kk + q4;
                    a[mt][0] = *(const uint32_t*)(ar);
                    a[mt][1] = *(const uint32_t*)(ar + 8 * PAD);
                    a[mt][2] = *(const uint32_t*)(ar + 16);
                    a[mt][3] = *(const uint32_t*)(ar + 8 * PAD + 16);
                }
#pragma unroll
                for (int n8 = 0; n8 < 2; ++n8) {
                    const char* bg = Bs + (wn * 16 + n8 * 8 + sub) * PAD + kk + q4;
                    uint32_t g0 = *(const uint32_t*)(bg);
                    uint32_t g1 = *(const uint32_t*)(bg + 16);
                    uint32_t u0 = *(const uint32_t*)(bg + 64 * PAD);
                    uint32_t u1 = *(const uint32_t*)(bg + 64 * PAD + 16);
#pragma unroll
                    for (int mt = 0; mt < 2; ++mt) {
                        mma_s8(accg[mt][n8], a[mt][0], a[mt][1], a[mt][2], a[mt][3], g0, g1);
                        mma_s8(accu[mt][n8], a[mt][0], a[mt][1], a[mt][2], a[mt][3], u0, u1);
                    }
                }
            }
            if (ks + 2 < NS1) {
                int s = (ks + 2) % 3;
                int kb = (ks + 2) * 64;
                CP16(dA + s * ST1, srcA + kb);
                CP16(dB + s * ST1, srcB + kb);
                CP16(dB + s * ST1 + 16, srcB + kb + 16);
            }
            CP_COMMIT();
        }

        const float* s13 = s13_all + (size_t)e * TWOI + z * 64;
#pragma unroll
        for (int mt = 0; mt < 2; ++mt) {
#pragma unroll
            for (int n8 = 0; n8 < 2; ++n8) {
                int col = wn * 16 + n8 * 8 + (lane & 3) * 2;
                float sg0 = s13[col], sg1 = s13[col + 1];
                float su0 = s13[col + I_], su1 = s13[col + I_ + 1];
#pragma unroll
                for (int h2 = 0; h2 < 2; ++h2) {
                    int row = wm * 32 + mt * 16 + sub + h2 * 8;
                    if (row < nt) {
                        float si = sin_s[row];
                        float g0 = (float)accg[mt][n8][h2 * 2 + 0] * si * sg0;
                        float g1 = (float)accg[mt][n8][h2 * 2 + 1] * si * sg1;
                        float u0 = (float)accu[mt][n8][h2 * 2 + 0] * si * su0;
                        float u1 = (float)accu[mt][n8][h2 * 2 + 1] * si * su1;
                        float a0 = g0 * __fdiv_rn(1.f, 1.f + expf(-g0)) * u0;
                        float a1 = g1 * __fdiv_rn(1.f, 1.f + expf(-g1)) * u1;
                        *(float2*)(g_act + (size_t)dst_s[row] * I_ + z * 64 + col) =
                            make_float2(a0, a1);
                    }
                }
            }
        }
    } else {
        // ---- dp4a role: i-cols [32,64) ----
        int col = 32 + (warp - 4) * 8 + (lane & 7);
        int rg = lane >> 3;
        int accg[16], accu[16];
#pragma unroll
        for (int r = 0; r < 16; ++r) { accg[r] = 0; accu[r] = 0; }

        for (int ks = 0; ks < NS1; ++ks) {
            CP_WAIT1();
            __syncthreads();
            const char* As = smem + (ks % 3) * ST1;
            const char* Bs = As + 5120;
#pragma unroll
            for (int j = 0; j < 4; ++j) {
                int kk4 = ((rg + j) & 3) * 16;
                int4 bg = *(const int4*)(Bs + col * PAD + kk4);
                int4 bu = *(const int4*)(Bs + (64 + col) * PAD + kk4);
#pragma unroll
                for (int r = 0; r < 16; ++r) {
                    int4 av = *(const int4*)(As + (rg * 16 + r) * PAD + kk4);
                    accg[r] = __dp4a(av.x, bg.x, accg[r]);
                    accg[r] = __dp4a(av.y, bg.y, accg[r]);
                    accg[r] = __dp4a(av.z, bg.z, accg[r]);
                    accg[r] = __dp4a(av.w, bg.w, accg[r]);
                    accu[r] = __dp4a(av.x, bu.x, accu[r]);
                    accu[r] = __dp4a(av.y, bu.y, accu[r]);
                    accu[r] = __dp4a(av.z, bu.z, accu[r]);
                    accu[r] = __dp4a(av.w, bu.w, accu[r]);
                }
            }
            if (ks + 2 < NS1) {
                int s = (ks + 2) % 3;
                int kb = (ks + 2) * 64;
                CP16(dA + s * ST1, srcA + kb);
                CP16(dB + s * ST1, srcB + kb);
                CP16(dB + s * ST1 + 16, srcB + kb + 16);
            }
            CP_COMMIT();
        }

        const float* s13 = s13_all + (size_t)e * TWOI + z * 64;
        float sg = s13[col], su = s13[col + I_];
#pragma unroll
        for (int r = 0; r < 16; ++r) {
            int row = rg * 16 + r;
            if (row < nt) {
                float si = sin_s[row];
                float g = (float)accg[r] * si * sg;
                float u = (float)accu[r] * si * su;
                g_act[(size_t)dst_s[row] * I_ + z * 64 + col] =
                    g * __fdiv_rn(1.f, 1.f + expf(-g)) * u;
            }
        }
    }
}

// ---------------- requant (+ fused zeroing of out) ----------------
__global__ __launch_bounds__(128) void requant_kernel(float* __restrict__ out) {
    // zero the output buffer (grid-stride; out untouched until gemm2)
    {
        size_t nidx = (size_t)gridDim.x * 128;
        for (size_t i = (size_t)blockIdx.x * 128 + threadIdx.x;
             i < (size_t)(T_ * H_) / 4; i += nidx)
            ((float4*)out)[i] = make_float4(0.f, 0.f, 0.f, 0.f);
    }
    int dst = blockIdx.x;
    const float* a = g_act + (size_t)dst * I_;
    int tid = threadIdx.x;
    float m = 0.f;
    for (int i = tid; i < I_; i += 128) m = fmaxf(m, fabsf(a[i]));
    __shared__ float red[4];
#pragma unroll
    for (int off = 16; off; off >>= 1) m = fmaxf(m, __shfl_down_sync(0xffffffffu, m, off));
    if ((tid & 31) == 0) red[tid >> 5] = m;
    __syncthreads();
    float mm = fmaxf(fmaxf(red[0], red[1]), fmaxf(red[2], red[3]));
    float sa = fmaxf(__fdiv_rn(mm, 127.f), 1e-8f);
    if (tid == 0) g_sa[dst] = sa;
    int8_t* q = g_qact + (size_t)dst * I_;
    for (int i = tid; i < I_; i += 128) {
        float v = fminf(fmaxf(rintf(__fdiv_rn(a[i], sa)), -127.f), 127.f);
        q[i] = (int8_t)v;
    }
}

// ===========================================================================
// GEMM2 hybrid (R10 config): M=64 x 128 h-cols. warps 0-3 mma (cols 0-63),
// warps 4-7 dp4a (cols 64-127). grid (64, E, 16). atomicAdd into out.
// ===========================================================================
#define ST2    15360
#define G2_META (3 * ST2)
#define G2_SMEM (G2_META + 1024)
#define NS2    22

__global__ __launch_bounds__(256, 2) void gemm2_mma(const float* __restrict__ s2_all,
                                                    float* __restrict__ out) {
    int e = blockIdx.y;
    int cnt = g_cnt[e];
    int m0 = blockIdx.x * 64;
    if (m0 >= cnt) return;
    int nt = min(64, cnt - m0);
    int z = blockIdx.z;

    extern __shared__ char smem[];
    uint32_t sb = smem_u32(smem);
    int* dst_s = (int*)(smem + G2_META);
    float* sc_s = (float*)(smem + G2_META + 256);
    int tid = threadIdx.x;

    if (tid < 64) {
        int packed; float gv;
        if (tid < nt) { packed = g_tok[e][m0 + tid]; gv = g_gate_arr[e][m0 + tid]; }
        else          { packed = g_tok[e][m0];       gv = 0.f; }
        dst_s[tid] = packed;
        sc_s[tid] = gv * g_sa[packed];
    }
    __syncthreads();

    const int8_t* w2 = g_w2 + (size_t)e * H_ * I_;
    int rA = tid >> 2, cA = (tid & 3) * 16;
    const int8_t* srcA = g_qact + (size_t)dst_s[rA] * I_ + cA;
    int rB = tid >> 1, cB = (tid & 1) * 32;
    const int8_t* srcB = w2 + (size_t)(z * 128 + rB) * I_ + cB;
    uint32_t dA = sb + rA * PAD + cA;
    uint32_t dB = sb + 5120 + rB * PAD + cB;

#pragma unroll
    for (int s = 0; s < 2; ++s) {
        CP16(dA + s * ST2, srcA + s * 64);
        CP16(dB + s * ST2, srcB + s * 64);
        CP16(dB + s * ST2 + 16, srcB + s * 64 + 16);
        CP_COMMIT();
    }

    int warp = tid >> 5, lane = tid & 31;

    if (warp < 4) {
        int wm = warp & 1, wv = warp >> 1;
        int sub = lane >> 2, q4 = (lane & 3) * 4;
        int acc[2][4][4];
#pragma unroll
        for (int mt = 0; mt < 2; ++mt)
#pragma unroll
            for (int n8 = 0; n8 < 4; ++n8)
#pragma unroll
                for (int r = 0; r < 4; ++r) acc[mt][n8][r] = 0;

        for (int ks = 0; ks < NS2; ++ks) {
            CP_WAIT1();
            __syncthreads();
            const char* As = smem + (ks % 3) * ST2;
            const char* Bs = As + 5120;
#pragma unroll
            for (int kk = 0; kk < 64; kk += 32) {
                uint32_t a[2][4];
#pragma unroll
                for (int mt = 0; mt < 2; ++mt) {
                    const char* ar = As + (wm * 32 + mt * 16 + sub) * PAD + kk + q4;
                    a[mt][0] = *(const uint32_t*)(ar);
                    a[mt][1] = *(const uint32_t*)(ar + 8 * PAD);
                    a[mt][2] = *(const uint32_t*)(ar + 16);
                    a[mt][3] = *(const uint32_t*)(ar + 8 * PAD + 16);
                }
#pragma unroll
                for (int n8 = 0; n8 < 4; ++n8) {
                    const char* br = Bs + (wv * 32 + n8 * 8 + sub) * PAD + kk + q4;
                    uint32_t b0 = *(const uint32_t*)(br);
                    uint32_t b1 = *(const uint32_t*)(br + 16);
#pragma unroll
                    for (int mt = 0; mt < 2; ++mt)
                        mma_s8(acc[mt][n8], a[mt][0], a[mt][1], a[mt][2], a[mt][3], b0, b1);
                }
            }
            if (ks + 2 < NS2) {
                int s = (ks + 2) % 3;
                int kb = (ks + 2) * 64;
                CP16(dA + s * ST2, srcA + kb);
                CP16(dB + s * ST2, srcB + kb);
                CP16(dB + s * ST2 + 16, srcB + kb + 16);
            }
            CP_COMMIT();
        }

        const float* s2w = s2_all + (size_t)e * H_ + z * 128;
#pragma unroll
        for (int mt = 0; mt < 2; ++mt) {
#pragma unroll
            for (int n8 = 0; n8 < 4; ++n8) {
                int col = wv * 32 + n8 * 8 + (lane & 3) * 2;
                float w0 = s2w[col], w1 = s2w[col + 1];
#pragma unroll
                for (int h2 = 0; h2 < 2; ++h2) {
                    int row = wm * 32 + mt * 16 + sub + h2 * 8;
                    if (row < nt) {
                        float sc = sc_s[row];
                        int t = dst_s[row] >> 1;
                        float* orow = out + (size_t)t * H_ + z * 128 + col;
                        atomicAdd(orow, (float)acc[mt][n8][h2 * 2 + 0] * sc * w0);
                        atomicAdd(orow + 1, (float)acc[mt][n8][h2 * 2 + 1] * sc * w1);
                    }
                }
            }
        }
    } else {
        int col = 64 + (warp - 4) * 16 + (lane & 15);
        int rg = lane >> 4;
        int acc[32];
#pragma unroll
        for (int r = 0; r < 32; ++r) acc[r] = 0;

        for (int ks = 0; ks < NS2; ++ks) {
            CP_WAIT1();
            __syncthreads();
            const char* As = smem + (ks % 3) * ST2;
            const char* Bs = As + 5120;
#pragma unroll
            for (int j = 0; j < 4; ++j) {
                int kk4 = ((rg * 2 + j) & 3) * 16;
                int4 bv = *(const int4*)(Bs + col * PAD + kk4);
#pragma unroll
                for (int r = 0; r < 32; ++r) {
                    int4 av = *(const int4*)(As + (rg * 32 + r) * PAD + kk4);
                    acc[r] = __dp4a(av.x, bv.x, acc[r]);
                    acc[r] = __dp4a(av.y, bv.y, acc[r]);
                    acc[r] = __dp4a(av.z, bv.z, acc[r]);
                    acc[r] = __dp4a(av.w, bv.w, acc[r]);
                }
            }
            if (ks + 2 < NS2) {
                int s = (ks + 2) % 3;
                int kb = (ks + 2) * 64;
                CP16(dA + s * ST2, srcA + kb);
                CP16(dB + s * ST2, srcB + kb);
                CP16(dB + s * ST2 + 16, srcB + kb + 16);
            }
            CP_COMMIT();
        }

        const float* s2w = s2_all + (size_t)e * H_ + z * 128;
        float w0 = s2w[col];
#pragma unroll
        for (int r = 0; r < 32; ++r) {
            int row = rg * 32 + r;
            if (row < nt) {
                float sc = sc_s[row];
                int t = dst_s[row] >> 1;
                atomicAdd(out + (size_t)t * H_ + z * 128 + col,
                          (float)acc[r] * sc * w0);
            }
        }
    }
}

// ---------------------------------------------------------------------------
extern "C" void kernel_launch(void* const* d_in, const int* in_sizes, int n_in,
                              void* d_out, int out_size) {
    const float* hid = nullptr;
    const float* gw = nullptr;
    const void* w13raw = nullptr;
    const float* s13 = nullptr;
    const void* w2raw = nullptr;
    const float* s2 = nullptr;
    for (int i = 0; i < n_in; ++i) {
        long long s = in_sizes[i];
        if (s == 8388608LL || s == 33554432LL) hid = (const float*)d_in[i];
        else if (s == 46137344LL || s == 184549376LL) w13raw = d_in[i];
        else if (s == 22528LL || s == 90112LL) s13 = (const float*)d_in[i];
        else if (s == 23068672LL || s == 92274688LL) w2raw = d_in[i];
        else if (s == 16384LL || s == 65536LL) {
            if (!gw) gw = (const float*)d_in[i];
            else s2 = (const float*)d_in[i];
        }
    }
    if (n_in >= 6) {
        if (!hid)    hid = (const float*)d_in[0];
        if (!gw)     gw = (const float*)d_in[1];
        if (!w13raw) w13raw = d_in[2];
        if (!s13)    s13 = (const float*)d_in[3];
        if (!w2raw)  w2raw = d_in[4];
        if (!s2)     s2 = (const float*)d_in[5];
    }
    float* out = (float*)d_out;

    cudaFuncSetAttribute(gemm1_mma, cudaFuncAttributeMaxDynamicSharedMemorySize, G1_SMEM);
    cudaFuncSetAttribute(gemm2_mma, cudaFuncAttributeMaxDynamicSharedMemorySize, G2_SMEM);

    convert_all_kernel<<<8192, 256>>>(w13raw, w2raw);     // 1
    gatequant_kernel<<<T_, 256>>>(hid, gw);               // 2
    dim3 g1(64, E_, 22);
    gemm1_mma<<<g1, 256, G1_SMEM>>>(s13);                 // 3
    requant_kernel<<<T_ * 2, 128>>>(out);                 // 4 (+ zero out)
    dim3 g2(64, E_, 16);
    gemm2_mma<<<g2, 256, G2_SMEM>>>(s2, out);             // 5
}